// round 7
// baseline (speedup 1.0000x reference)
#include <cuda_runtime.h>
#include <cuda_bf16.h>
#include <math.h>

#define BB     2
#define CC     256
#define NQ     4096
#define HEADS  4
#define DH     64
#define KK     64
#define GROUPS 32
#define CPG    8
#define EPS    1e-6f

#define PAD_A  136      // [c][n] layout pad
#define PAD_B  36       // [row][c] layout pad

// Scratch (device globals; no allocation allowed)
__device__ float         g_qt[BB*NQ*CC];   // Q fp32, [b][n][c]  c = head*64 + d
__device__ __nv_bfloat16 g_kb[BB*NQ*CC];   // K bf16, [b][n][c]
__device__ __nv_bfloat16 g_vb[BB*NQ*CC];   // V bf16, [b][n][c]
__device__ float         g_at[BB*NQ*CC];   // attn out, [b][n][c] c = d*HEADS + h
__device__ float         g_mean[BB][GROUPS];
__device__ float         g_rstd[BB][GROUPS];
__device__ float         g_wp[BB*3*CC*CC]; // GN-folded weights [b][which][o][c]
__device__ float         g_bp[BB*3*CC];    // GN-folded biases

// ---------------------------------------------------------------------------
// helpers
// ---------------------------------------------------------------------------
__device__ __forceinline__ void mma1688(float d[4], const unsigned a[4],
                                        const unsigned b[2]) {
    asm("mma.sync.aligned.m16n8k8.row.col.f32.tf32.tf32.f32 "
        "{%0,%1,%2,%3}, {%4,%5,%6,%7}, {%8,%9}, {%0,%1,%2,%3};"
        : "+f"(d[0]), "+f"(d[1]), "+f"(d[2]), "+f"(d[3])
        : "r"(a[0]), "r"(a[1]), "r"(a[2]), "r"(a[3]),
          "r"(b[0]), "r"(b[1]));
}

__device__ __forceinline__ void cp16(unsigned dst, const void* src) {
    asm volatile("cp.async.cg.shared.global [%0], [%1], 16;"
                 :: "r"(dst), "l"(src));
}
#define CP_COMMIT() asm volatile("cp.async.commit_group;")
#define CP_WAIT(n)  asm volatile("cp.async.wait_group %0;" :: "n"(n))

__device__ __forceinline__ void unpack8(float4 u, float* f) {
    const __nv_bfloat162* p = (const __nv_bfloat162*)&u;
    float2 a = __bfloat1622float2(p[0]);
    float2 b = __bfloat1622float2(p[1]);
    float2 c = __bfloat1622float2(p[2]);
    float2 d = __bfloat1622float2(p[3]);
    f[0]=a.x; f[1]=a.y; f[2]=b.x; f[3]=b.y;
    f[4]=c.x; f[5]=c.y; f[6]=d.x; f[7]=d.y;
}

// ---------------------------------------------------------------------------
// GroupNorm statistics only: grid (GROUPS, B), block 256
// ---------------------------------------------------------------------------
__global__ void gn_stats(const float* __restrict__ x)
{
    const int g = blockIdx.x, b = blockIdx.y;
    const float* xp = x + ((size_t)b*CC + g*CPG) * NQ;
    const int tid = threadIdx.x;
    const int NE  = CPG * NQ;

    float s = 0.f, s2 = 0.f;
    for (int i = tid; i < NE; i += 256) {
        float v = xp[i];
        s += v; s2 += v * v;
    }
    #pragma unroll
    for (int o = 16; o; o >>= 1) {
        s  += __shfl_xor_sync(~0u, s,  o);
        s2 += __shfl_xor_sync(~0u, s2, o);
    }
    __shared__ float shs[8], shs2[8];
    int w = tid >> 5, l = tid & 31;
    if (l == 0) { shs[w] = s; shs2[w] = s2; }
    __syncthreads();
    if (tid == 0) {
        float a = 0.f, c = 0.f;
        #pragma unroll
        for (int i = 0; i < 8; i++) { a += shs[i]; c += shs2[i]; }
        float m   = a / NE;
        float var = c / NE - m * m;
        g_mean[b][g] = m;
        g_rstd[b][g] = rsqrtf(var + EPS);
    }
}

// ---------------------------------------------------------------------------
// Fold GN into QKV weights. grid (3, B), block 256.
// ---------------------------------------------------------------------------
__global__ void wprep(const float* __restrict__ wq, const float* __restrict__ bq,
                      const float* __restrict__ wk, const float* __restrict__ bk,
                      const float* __restrict__ wv, const float* __restrict__ bv,
                      const float* __restrict__ gsc, const float* __restrict__ gbi)
{
    const int which = blockIdx.x, b = blockIdx.y;
    const float* W    = which == 0 ? wq : which == 1 ? wk : wv;
    const float* bias = which == 0 ? bq : which == 1 ? bk : bv;

    __shared__ float coef[CC], sub[CC];
    const int tid = threadIdx.x;
    {
        int c = tid;
        int g = c >> 3;
        float r = g_rstd[b][g], m = g_mean[b][g];
        float sc = gsc[c];
        coef[c] = sc * r;
        sub[c]  = gbi[c] - m * r * sc;
    }
    __syncthreads();

    float* Wp = g_wp + (size_t)(b*3 + which) * CC * CC;
    float* bp = g_bp + (b*3 + which) * CC;
    const int wid = tid >> 5, lane = tid & 31;

    for (int o = wid; o < CC; o += 8) {
        float acc = 0.f;
        #pragma unroll
        for (int cb = 0; cb < CC; cb += 32) {
            int c = cb + lane;
            float w = W[(size_t)o * CC + c];
            Wp[(size_t)o * CC + c] = w * coef[c];
            acc += w * sub[c];
        }
        #pragma unroll
        for (int off = 16; off; off >>= 1)
            acc += __shfl_xor_sync(~0u, acc, off);
        if (lane == 0) bp[o] = bias[o] + acc;
    }
}

// ---------------------------------------------------------------------------
// Fused QKV GEMM (tf32 MMA, cp.async double-buffered, GN folded):
// O[b][n][o] = sum_c W'[o][c] * x[b][c][n] + bias'[o]
// Tile 128(n=M) x 128(o=N), 256 threads (8 warps 2x4). grid (NQ/128, 6, B).
// ---------------------------------------------------------------------------
#define QKV_SMEM ((2*32*PAD_A + 2*128*PAD_B) * 4)

__global__ void __launch_bounds__(256, 2)
gemm_qkv(const float* __restrict__ x)
{
    extern __shared__ unsigned smem_dyn[];
    unsigned* As = smem_dyn;                 // [2][32][PAD_A]  x  [c][n]
    unsigned* Bs = smem_dyn + 2*32*PAD_A;    // [2][128][PAD_B] W' [o][c]

    const int nb    = blockIdx.x * 128;
    const int which = blockIdx.y >> 1;
    const int ob    = (blockIdx.y & 1) * 128;
    const int b     = blockIdx.z;

    const float* W    = g_wp + (size_t)(b*3 + which) * CC * CC;
    const float* bias = g_bp + (b*3 + which) * CC;
    const float* X    = x    + (size_t)b * CC * NQ;   // [c][n]

    const int tid  = threadIdx.x;
    const int wid  = tid >> 5, lane = tid & 31;
    const int wm   = wid & 1,  wn   = wid >> 1;
    const int g    = lane >> 2, t   = lane & 3;

    const unsigned as_base = (unsigned)__cvta_generic_to_shared(As);
    const unsigned bs_base = (unsigned)__cvta_generic_to_shared(Bs);

    const int a_c = tid >> 5, a_seg = tid & 31;
    const int b_o = tid >> 3, b_seg = tid & 7;

    #define LOAD_STAGE(s, c0)                                                  \
    {                                                                          \
        _Pragma("unroll")                                                      \
        for (int j = 0; j < 4; j++) {                                          \
            int c = a_c + j * 8;                                               \
            cp16(as_base + (((s)*32 + c) * PAD_A + a_seg * 4) * 4,             \
                 X + (size_t)((c0) + c) * NQ + nb + a_seg * 4);                \
        }                                                                      \
        _Pragma("unroll")                                                      \
        for (int j = 0; j < 4; j++) {                                          \
            int o = b_o + j * 32;                                              \
            cp16(bs_base + (((s)*128 + o) * PAD_B + b_seg * 4) * 4,            \
                 W + (size_t)(ob + o) * CC + (c0) + b_seg * 4);                \
        }                                                                      \
        CP_COMMIT();                                                           \
    }

    float acc[4][4][4];
    #pragma unroll
    for (int i = 0; i < 4; i++)
        #pragma unroll
        for (int j = 0; j < 4; j++)
            #pragma unroll
            for (int r = 0; r < 4; r++) acc[i][j][r] = 0.f;

    LOAD_STAGE(0, 0);

    #pragma unroll
    for (int ks = 0; ks < 8; ks++) {
        const int cur = ks & 1;
        if (ks < 7) {
            LOAD_STAGE(1 - cur, (ks + 1) * 32);
            CP_WAIT(1);
        } else {
            CP_WAIT(0);
        }
        __syncthreads();

        #pragma unroll
        for (int k8 = 0; k8 < 32; k8 += 8) {
            unsigned afr[4][4], bfr[4][2];
            #pragma unroll
            for (int mt = 0; mt < 4; mt++) {
                int row = wm * 64 + mt * 16;
                afr[mt][0] = As[(cur*32 + k8 + t    ) * PAD_A + row + g    ];
                afr[mt][1] = As[(cur*32 + k8 + t    ) * PAD_A + row + 8 + g];
                afr[mt][2] = As[(cur*32 + k8 + 4 + t) * PAD_A + row + g    ];
                afr[mt][3] = As[(cur*32 + k8 + 4 + t) * PAD_A + row + 8 + g];
            }
            #pragma unroll
            for (int nt = 0; nt < 4; nt++) {
                int col = wn * 32 + nt * 8;
                bfr[nt][0] = Bs[(cur*128 + col + g) * PAD_B + k8 + t    ];
                bfr[nt][1] = Bs[(cur*128 + col + g) * PAD_B + k8 + 4 + t];
            }
            #pragma unroll
            for (int mt = 0; mt < 4; mt++)
                #pragma unroll
                for (int nt = 0; nt < 4; nt++)
                    mma1688(acc[mt][nt], afr[mt], bfr[nt]);
        }
        __syncthreads();
    }
    #undef LOAD_STAGE

    if (which == 0) {
        float* O = g_qt + (size_t)b * NQ * CC;
        #pragma unroll
        for (int nt = 0; nt < 4; nt++) {
            int o = ob + wn * 32 + nt * 8 + 2 * t;
            float bb0 = bias[o], bb1 = bias[o + 1];
            #pragma unroll
            for (int mt = 0; mt < 4; mt++) {
                int n0 = nb + wm * 64 + mt * 16 + g;
                float2 v0 = {acc[mt][nt][0] + bb0, acc[mt][nt][1] + bb1};
                float2 v1 = {acc[mt][nt][2] + bb0, acc[mt][nt][3] + bb1};
                *(float2*)&O[(size_t)n0 * CC + o]       = v0;
                *(float2*)&O[(size_t)(n0 + 8) * CC + o] = v1;
            }
        }
    } else {
        __nv_bfloat16* O = (which == 1 ? g_kb : g_vb) + (size_t)b * NQ * CC;
        #pragma unroll
        for (int nt = 0; nt < 4; nt++) {
            int o = ob + wn * 32 + nt * 8 + 2 * t;
            float bb0 = bias[o], bb1 = bias[o + 1];
            #pragma unroll
            for (int mt = 0; mt < 4; mt++) {
                int n0 = nb + wm * 64 + mt * 16 + g;
                __nv_bfloat162 v0 = {__float2bfloat16_rn(acc[mt][nt][0] + bb0),
                                     __float2bfloat16_rn(acc[mt][nt][1] + bb1)};
                __nv_bfloat162 v1 = {__float2bfloat16_rn(acc[mt][nt][2] + bb0),
                                     __float2bfloat16_rn(acc[mt][nt][3] + bb1)};
                *(__nv_bfloat162*)&O[(size_t)n0 * CC + o]       = v0;
                *(__nv_bfloat162*)&O[(size_t)(n0 + 8) * CC + o] = v1;
            }
        }
    }
}

// ---------------------------------------------------------------------------
// Sparse attention v3: one warp per (b, n), shuffle-free via smem.
// Phase 1: lane 8h+i computes FULL logits itself for head h, keys i+8j
//          (q staged in smem, 4-way broadcast conflict-free).
// Softmax: 3+3 shfl within disjoint 8-lane head groups (parallel).
// Phase 2: weights+indices via smem (broadcast LDS), coalesced V rows.
// ---------------------------------------------------------------------------
__global__ void __launch_bounds__(256)
attn_kernel(const int* __restrict__ mask, const int* __restrict__ aidx)
{
    __shared__ float sq  [8][4][68];   // q per warp, per head (padded rows)
    __shared__ int   sidx[8][64];      // gathered index, -1 if masked
    __shared__ float sw  [8][64][4];   // softmax weight per key per head

    const int wrp = threadIdx.x >> 5, l = threadIdx.x & 31;
    const int gw = blockIdx.x * 8 + wrp;
    const int n  = gw & (NQ - 1);
    const int b  = gw >> 12;

    const float* qp = g_qt + ((size_t)b * NQ + n) * CC;

    // stage q: 8 scalar coalesced loads -> conflict-free STS
    #pragma unroll
    for (int j = 0; j < 8; j++) {
        int c = l + 32 * j;
        sq[wrp][c >> 6][c & 63] = qp[c];
    }
    // stage indices with mask sentinel
    {
        int i0 = aidx[n * KK + l];
        int i1 = aidx[n * KK + l + 32];
        int m0 = mask[n * KK + l];
        int m1 = mask[n * KK + l + 32];
        sidx[wrp][l]      = m0 ? i0 : -1;
        sidx[wrp][l + 32] = m1 ? i1 : -1;
    }
    __syncwarp();

    const int h = l >> 3, i = l & 7;
    const float* qh = sq[wrp][h];
    const __nv_bfloat16* Kh = g_kb + (size_t)b * NQ * CC + h * DH;
    const __nv_bfloat16* Vb = g_vb + (size_t)b * NQ * CC;

    // ---- Phase 1: full per-lane dot products, 8 keys per lane ----
    float lg[8];
    #pragma unroll
    for (int j = 0; j < 8; j++) {
        const int key = i + 8 * j;
        const int idx = sidx[wrp][key];
        float p = -INFINITY;
        if (idx >= 0) {
            const float4* kr = (const float4*)(Kh + (size_t)idx * CC);
            p = 0.f;
            #pragma unroll
            for (int ch = 0; ch < 8; ch++) {
                float kf[8];
                unpack8(kr[ch], kf);
                #pragma unroll
                for (int u = 0; u < 8; u++)
                    p += qh[ch * 8 + u] * kf[u];
            }
        }
        lg[j] = p;
    }

    // ---- softmax per head (8-lane groups, disjoint => parallel) ----
    float mx = lg[0];
    #pragma unroll
    for (int j = 1; j < 8; j++) mx = fmaxf(mx, lg[j]);
    mx = fmaxf(mx, __shfl_xor_sync(~0u, mx, 4));
    mx = fmaxf(mx, __shfl_xor_sync(~0u, mx, 2));
    mx = fmaxf(mx, __shfl_xor_sync(~0u, mx, 1));

    float e[8], s = 0.f;
    #pragma unroll
    for (int j = 0; j < 8; j++) { e[j] = __expf(lg[j] - mx); s += e[j]; }
    s += __shfl_xor_sync(~0u, s, 4);
    s += __shfl_xor_sync(~0u, s, 2);
    s += __shfl_xor_sync(~0u, s, 1);
    const float inv = 1.f / s;

    #pragma unroll
    for (int j = 0; j < 8; j++)
        sw[wrp][i + 8 * j][h] = e[j] * inv;
    __syncwarp();

    // ---- Phase 2: V accumulation, lane l owns channels 8l..8l+7 ----
    float acc[8] = {0.f,0.f,0.f,0.f,0.f,0.f,0.f,0.f};
    const int hsel = l >> 3;

    #pragma unroll 4
    for (int key = 0; key < KK; key++) {
        const int idx = sidx[wrp][key];      // broadcast LDS
        if (idx < 0) continue;               // warp-uniform skip
        const float wv = sw[wrp][key][hsel]; // 4-addr broadcast LDS
        float vf[8];
        unpack8(((const float4*)(Vb + (size_t)idx * CC))[l], vf);
        #pragma unroll
        for (int u = 0; u < 8; u++) acc[u] += wv * vf[u];
    }

    // ---- store, interleaved channel order c_out = d*HEADS + h ----
    float* at = g_at + ((size_t)b * NQ + n) * CC;
    #pragma unroll
    for (int j = 0; j < 8; j++) {
        int c = 8 * l + j;                   // c = 64*h + d
        at[(c & 63) * HEADS + hsel] = acc[j];
    }
}

// ---------------------------------------------------------------------------
// Output projection + residual (tf32 MMA, cp.async double-buffered):
// Tile 128(o=M) x 128(n=N), 256 threads. grid (NQ/128, CC/128, B).
// ---------------------------------------------------------------------------
#define OUT_SMEM ((2*128*PAD_B * 2) * 4)

__global__ void __launch_bounds__(256, 2)
gemm_out(const float* __restrict__ Wo, const float* __restrict__ bo,
         const float* __restrict__ x,  float* __restrict__ out)
{
    extern __shared__ unsigned smem_dyn[];
    unsigned* As = smem_dyn;                   // [2][128][PAD_B]  Wo [o][c]
    unsigned* Bs = smem_dyn + 2*128*PAD_B;     // [2][128][PAD_B]  at [n][c]

    const int nb = blockIdx.x * 128, ob = blockIdx.y * 128, b = blockIdx.z;
    const float* A = g_at + (size_t)b * NQ * CC;   // [n][c]

    const int tid  = threadIdx.x;
    const int wid  = tid >> 5, lane = tid & 31;
    const int wm   = wid & 1,  wn   = wid >> 1;
    const int g    = lane >> 2, t   = lane & 3;

    const unsigned as_base = (unsigned)__cvta_generic_to_shared(As);
    const unsigned bs_base = (unsigned)__cvta_generic_to_shared(Bs);

    const int r_o = tid >> 3, r_seg = tid & 7;

    #define LOAD_STAGE(s, c0)                                                  \
    {                                                                          \
        _Pragma("unroll")                                                      \
        for (int j = 0; j < 4; j++) {                                          \
            int o = r_o + j * 32;                                              \
            cp16(as_base + (((s)*128 + o) * PAD_B + r_seg * 4) * 4,            \
                 Wo + (size_t)(ob + o) * CC + (c0) + r_seg * 4);               \
        }                                                                      \
        _Pragma("unroll")                                                      \
        for (int j = 0; j < 4; j++) {                                          \
            int n = r_o + j * 32;                                              \
            cp16(bs_base + (((s)*128 + n) * PAD_B + r_seg * 4) * 4,            \
                 A + (size_t)(nb + n) * CC + (c0) + r_seg * 4);                \
        }                                                                      \
        CP_COMMIT();                                                           \
    }

    float acc[4][4][4];
    #pragma unroll
    for (int i = 0; i < 4; i++)
        #pragma unroll
        for (int j = 0; j < 4; j++)
            #pragma unroll
            for (int r = 0; r < 4; r++) acc[i][j][r] = 0.f;

    LOAD_STAGE(0, 0);

    #pragma unroll
    for (int ks = 0; ks < 8; ks++) {
        const int cur = ks & 1;
        if (ks < 7) {
            LOAD_STAGE(1 - cur, (ks + 1) * 32);
            CP_WAIT(1);
        } else {
            CP_WAIT(0);
        }
        __syncthreads();

        #pragma unroll
        for (int k8 = 0; k8 < 32; k8 += 8) {
            unsigned afr[4][4], bfr[4][2];
            #pragma unroll
            for (int mt = 0; mt < 4; mt++) {
                int row = wm * 64 + mt * 16;
                afr[mt][0] = As[(cur*128 + row + g    ) * PAD_B + k8 + t    ];
                afr[mt][1] = As[(cur*128 + row + 8 + g) * PAD_B + k8 + t    ];
                afr[mt][2] = As[(cur*128 + row + g    ) * PAD_B + k8 + 4 + t];
                afr[mt][3] = As[(cur*128 + row + 8 + g) * PAD_B + k8 + 4 + t];
            }
            #pragma unroll
            for (int nt = 0; nt < 4; nt++) {
                int col = wn * 32 + nt * 8;
                bfr[nt][0] = Bs[(cur*128 + col + g) * PAD_B + k8 + t    ];
                bfr[nt][1] = Bs[(cur*128 + col + g) * PAD_B + k8 + 4 + t];
            }
            #pragma unroll
            for (int mt = 0; mt < 4; mt++)
                #pragma unroll
                for (int nt = 0; nt < 4; nt++)
                    mma1688(acc[mt][nt], afr[mt], bfr[nt]);
        }
        __syncthreads();
    }
    #undef LOAD_STAGE

    const float* xp = x   + (size_t)b * CC * NQ;
    float*       op = out + (size_t)b * CC * NQ;
    #pragma unroll
    for (int mt = 0; mt < 4; mt++) {
        int o0 = ob + wm * 64 + mt * 16 + g;
        float bb0 = bo[o0], bb1 = bo[o0 + 8];
        #pragma unroll
        for (int nt = 0; nt < 4; nt++) {
            int n = nb + wn * 32 + nt * 8 + 2 * t;
            size_t base0 = (size_t)o0 * NQ + n;
            size_t base1 = (size_t)(o0 + 8) * NQ + n;
            float2 x0 = *(const float2*)&xp[base0];
            float2 x1 = *(const float2*)&xp[base1];
            float2 v0 = {acc[mt][nt][0] + bb0 + x0.x, acc[mt][nt][1] + bb0 + x0.y};
            float2 v1 = {acc[mt][nt][2] + bb1 + x1.x, acc[mt][nt][3] + bb1 + x1.y};
            *(float2*)&op[base0] = v0;
            *(float2*)&op[base1] = v1;
        }
    }
}

// ---------------------------------------------------------------------------
extern "C" void kernel_launch(void* const* d_in, const int* in_sizes, int n_in,
                              void* d_out, int out_size)
{
    const float* x    = (const float*)d_in[0];
    const int*   mask = (const int*)  d_in[1];
    const int*   aidx = (const int*)  d_in[2];
    const float* gsc  = (const float*)d_in[3];
    const float* gbi  = (const float*)d_in[4];
    const float* wq   = (const float*)d_in[5];
    const float* bq   = (const float*)d_in[6];
    const float* wk   = (const float*)d_in[7];
    const float* bk   = (const float*)d_in[8];
    const float* wv   = (const float*)d_in[9];
    const float* bv   = (const float*)d_in[10];
    const float* wo   = (const float*)d_in[11];
    const float* bo   = (const float*)d_in[12];
    float* out = (float*)d_out;

    cudaFuncSetAttribute(gemm_qkv, cudaFuncAttributeMaxDynamicSharedMemorySize,
                         QKV_SMEM);
    cudaFuncSetAttribute(gemm_out, cudaFuncAttributeMaxDynamicSharedMemorySize,
                         OUT_SMEM);

    gn_stats<<<dim3(GROUPS, BB), 256>>>(x);

    wprep<<<dim3(3, BB), 256>>>(wq, bq, wk, bk, wv, bv, gsc, gbi);

    gemm_qkv<<<dim3(NQ / 128, 6, BB), 256, QKV_SMEM>>>(x);

    attn_kernel<<<BB * NQ / 8, 256>>>(mask, aidx);

    gemm_out<<<dim3(NQ / 128, CC / 128, BB), 256, OUT_SMEM>>>(wo, bo, x, out);
}

// round 8
// speedup vs baseline: 1.2080x; 1.2080x over previous
#include <cuda_runtime.h>
#include <cuda_bf16.h>
#include <math.h>

#define BB     2
#define CC     256
#define NQ     4096
#define HEADS  4
#define DH     64
#define KK     64
#define GROUPS 32
#define CPG    8
#define EPS    1e-6f

#define PAD_A  136      // [c][n] layout pad
#define PAD_B  36       // [row][c] layout pad

// Scratch (device globals; no allocation allowed)
__device__ float         g_qt[BB*NQ*CC];   // Q fp32, [b][n][c]  c = head*64 + d
__device__ __nv_bfloat16 g_kb[BB*NQ*CC];   // K bf16, [b][n][c]
__device__ __nv_bfloat16 g_vb[BB*NQ*CC];   // V bf16, [b][n][c]
__device__ float         g_at[BB*NQ*CC];   // attn out, [b][n][c] c = d*HEADS + h
__device__ float         g_mean[BB][GROUPS];
__device__ float         g_rstd[BB][GROUPS];
__device__ float         g_wp[BB*3*CC*CC]; // GN-folded weights [b][which][o][c]
__device__ float         g_bp[BB*3*CC];    // GN-folded biases

// ---------------------------------------------------------------------------
// helpers
// ---------------------------------------------------------------------------
__device__ __forceinline__ void mma1688(float d[4], const unsigned a[4],
                                        const unsigned b[2]) {
    asm("mma.sync.aligned.m16n8k8.row.col.f32.tf32.tf32.f32 "
        "{%0,%1,%2,%3}, {%4,%5,%6,%7}, {%8,%9}, {%0,%1,%2,%3};"
        : "+f"(d[0]), "+f"(d[1]), "+f"(d[2]), "+f"(d[3])
        : "r"(a[0]), "r"(a[1]), "r"(a[2]), "r"(a[3]),
          "r"(b[0]), "r"(b[1]));
}

__device__ __forceinline__ void cp16(unsigned dst, const void* src) {
    asm volatile("cp.async.cg.shared.global [%0], [%1], 16;"
                 :: "r"(dst), "l"(src));
}
#define CP_COMMIT() asm volatile("cp.async.commit_group;")
#define CP_WAIT(n)  asm volatile("cp.async.wait_group %0;" :: "n"(n))

__device__ __forceinline__ void unpack8(float4 u, float* f) {
    const __nv_bfloat162* p = (const __nv_bfloat162*)&u;
    float2 a = __bfloat1622float2(p[0]);
    float2 b = __bfloat1622float2(p[1]);
    float2 c = __bfloat1622float2(p[2]);
    float2 d = __bfloat1622float2(p[3]);
    f[0]=a.x; f[1]=a.y; f[2]=b.x; f[3]=b.y;
    f[4]=c.x; f[5]=c.y; f[6]=d.x; f[7]=d.y;
}

// ---------------------------------------------------------------------------
// GroupNorm statistics only: grid (GROUPS, B), block 256
// ---------------------------------------------------------------------------
__global__ void gn_stats(const float* __restrict__ x)
{
    const int g = blockIdx.x, b = blockIdx.y;
    const float* xp = x + ((size_t)b*CC + g*CPG) * NQ;
    const int tid = threadIdx.x;
    const int NE  = CPG * NQ;

    float s = 0.f, s2 = 0.f;
    for (int i = tid; i < NE; i += 256) {
        float v = xp[i];
        s += v; s2 += v * v;
    }
    #pragma unroll
    for (int o = 16; o; o >>= 1) {
        s  += __shfl_xor_sync(~0u, s,  o);
        s2 += __shfl_xor_sync(~0u, s2, o);
    }
    __shared__ float shs[8], shs2[8];
    int w = tid >> 5, l = tid & 31;
    if (l == 0) { shs[w] = s; shs2[w] = s2; }
    __syncthreads();
    if (tid == 0) {
        float a = 0.f, c = 0.f;
        #pragma unroll
        for (int i = 0; i < 8; i++) { a += shs[i]; c += shs2[i]; }
        float m   = a / NE;
        float var = c / NE - m * m;
        g_mean[b][g] = m;
        g_rstd[b][g] = rsqrtf(var + EPS);
    }
}

// ---------------------------------------------------------------------------
// Fold GN into QKV weights. grid (3, B), block 256.
// ---------------------------------------------------------------------------
__global__ void wprep(const float* __restrict__ wq, const float* __restrict__ bq,
                      const float* __restrict__ wk, const float* __restrict__ bk,
                      const float* __restrict__ wv, const float* __restrict__ bv,
                      const float* __restrict__ gsc, const float* __restrict__ gbi)
{
    const int which = blockIdx.x, b = blockIdx.y;
    const float* W    = which == 0 ? wq : which == 1 ? wk : wv;
    const float* bias = which == 0 ? bq : which == 1 ? bk : bv;

    __shared__ float coef[CC], sub[CC];
    const int tid = threadIdx.x;
    {
        int c = tid;
        int g = c >> 3;
        float r = g_rstd[b][g], m = g_mean[b][g];
        float sc = gsc[c];
        coef[c] = sc * r;
        sub[c]  = gbi[c] - m * r * sc;
    }
    __syncthreads();

    float* Wp = g_wp + (size_t)(b*3 + which) * CC * CC;
    float* bp = g_bp + (b*3 + which) * CC;
    const int wid = tid >> 5, lane = tid & 31;

    for (int o = wid; o < CC; o += 8) {
        float acc = 0.f;
        #pragma unroll
        for (int cb = 0; cb < CC; cb += 32) {
            int c = cb + lane;
            float w = W[(size_t)o * CC + c];
            Wp[(size_t)o * CC + c] = w * coef[c];
            acc += w * sub[c];
        }
        #pragma unroll
        for (int off = 16; off; off >>= 1)
            acc += __shfl_xor_sync(~0u, acc, off);
        if (lane == 0) bp[o] = bias[o] + acc;
    }
}

// ---------------------------------------------------------------------------
// Fused QKV GEMM (tf32 MMA, cp.async double-buffered, GN folded):
// O[b][n][o] = sum_c W'[o][c] * x[b][c][n] + bias'[o]
// Tile 128(n=M) x 128(o=N), 256 threads (8 warps 2x4). grid (NQ/128, 6, B).
// ---------------------------------------------------------------------------
#define QKV_SMEM ((2*32*PAD_A + 2*128*PAD_B) * 4)

__global__ void __launch_bounds__(256)
gemm_qkv(const float* __restrict__ x)
{
    extern __shared__ unsigned smem_dyn[];
    unsigned* As = smem_dyn;                 // [2][32][PAD_A]  x  [c][n]
    unsigned* Bs = smem_dyn + 2*32*PAD_A;    // [2][128][PAD_B] W' [o][c]

    const int nb    = blockIdx.x * 128;
    const int which = blockIdx.y >> 1;
    const int ob    = (blockIdx.y & 1) * 128;
    const int b     = blockIdx.z;

    const float* W    = g_wp + (size_t)(b*3 + which) * CC * CC;
    const float* bias = g_bp + (b*3 + which) * CC;
    const float* X    = x    + (size_t)b * CC * NQ;   // [c][n]

    const int tid  = threadIdx.x;
    const int wid  = tid >> 5, lane = tid & 31;
    const int wm   = wid & 1,  wn   = wid >> 1;
    const int g    = lane >> 2, t   = lane & 3;

    const unsigned as_base = (unsigned)__cvta_generic_to_shared(As);
    const unsigned bs_base = (unsigned)__cvta_generic_to_shared(Bs);

    const int a_c = tid >> 5, a_seg = tid & 31;
    const int b_o = tid >> 3, b_seg = tid & 7;

    #define LOAD_STAGE(s, c0)                                                  \
    {                                                                          \
        _Pragma("unroll")                                                      \
        for (int j = 0; j < 4; j++) {                                          \
            int c = a_c + j * 8;                                               \
            cp16(as_base + (((s)*32 + c) * PAD_A + a_seg * 4) * 4,             \
                 X + (size_t)((c0) + c) * NQ + nb + a_seg * 4);                \
        }                                                                      \
        _Pragma("unroll")                                                      \
        for (int j = 0; j < 4; j++) {                                          \
            int o = b_o + j * 32;                                              \
            cp16(bs_base + (((s)*128 + o) * PAD_B + b_seg * 4) * 4,            \
                 W + (size_t)(ob + o) * CC + (c0) + b_seg * 4);                \
        }                                                                      \
        CP_COMMIT();                                                           \
    }

    float acc[4][4][4];
    #pragma unroll
    for (int i = 0; i < 4; i++)
        #pragma unroll
        for (int j = 0; j < 4; j++)
            #pragma unroll
            for (int r = 0; r < 4; r++) acc[i][j][r] = 0.f;

    LOAD_STAGE(0, 0);

    #pragma unroll
    for (int ks = 0; ks < 8; ks++) {
        const int cur = ks & 1;
        if (ks < 7) {
            LOAD_STAGE(1 - cur, (ks + 1) * 32);
            CP_WAIT(1);
        } else {
            CP_WAIT(0);
        }
        __syncthreads();

        #pragma unroll
        for (int k8 = 0; k8 < 32; k8 += 8) {
            unsigned afr[4][4], bfr[4][2];
            #pragma unroll
            for (int mt = 0; mt < 4; mt++) {
                int row = wm * 64 + mt * 16;
                afr[mt][0] = As[(cur*32 + k8 + t    ) * PAD_A + row + g    ];
                afr[mt][1] = As[(cur*32 + k8 + t    ) * PAD_A + row + 8 + g];
                afr[mt][2] = As[(cur*32 + k8 + 4 + t) * PAD_A + row + g    ];
                afr[mt][3] = As[(cur*32 + k8 + 4 + t) * PAD_A + row + 8 + g];
            }
            #pragma unroll
            for (int nt = 0; nt < 4; nt++) {
                int col = wn * 32 + nt * 8;
                bfr[nt][0] = Bs[(cur*128 + col + g) * PAD_B + k8 + t    ];
                bfr[nt][1] = Bs[(cur*128 + col + g) * PAD_B + k8 + 4 + t];
            }
            #pragma unroll
            for (int mt = 0; mt < 4; mt++)
                #pragma unroll
                for (int nt = 0; nt < 4; nt++)
                    mma1688(acc[mt][nt], afr[mt], bfr[nt]);
        }
        __syncthreads();
    }
    #undef LOAD_STAGE

    if (which == 0) {
        float* O = g_qt + (size_t)b * NQ * CC;
        #pragma unroll
        for (int nt = 0; nt < 4; nt++) {
            int o = ob + wn * 32 + nt * 8 + 2 * t;
            float bb0 = bias[o], bb1 = bias[o + 1];
            #pragma unroll
            for (int mt = 0; mt < 4; mt++) {
                int n0 = nb + wm * 64 + mt * 16 + g;
                float2 v0 = {acc[mt][nt][0] + bb0, acc[mt][nt][1] + bb1};
                float2 v1 = {acc[mt][nt][2] + bb0, acc[mt][nt][3] + bb1};
                *(float2*)&O[(size_t)n0 * CC + o]       = v0;
                *(float2*)&O[(size_t)(n0 + 8) * CC + o] = v1;
            }
        }
    } else {
        __nv_bfloat16* O = (which == 1 ? g_kb : g_vb) + (size_t)b * NQ * CC;
        #pragma unroll
        for (int nt = 0; nt < 4; nt++) {
            int o = ob + wn * 32 + nt * 8 + 2 * t;
            float bb0 = bias[o], bb1 = bias[o + 1];
            #pragma unroll
            for (int mt = 0; mt < 4; mt++) {
                int n0 = nb + wm * 64 + mt * 16 + g;
                __nv_bfloat162 v0 = {__float2bfloat16_rn(acc[mt][nt][0] + bb0),
                                     __float2bfloat16_rn(acc[mt][nt][1] + bb1)};
                __nv_bfloat162 v1 = {__float2bfloat16_rn(acc[mt][nt][2] + bb0),
                                     __float2bfloat16_rn(acc[mt][nt][3] + bb1)};
                *(__nv_bfloat162*)&O[(size_t)n0 * CC + o]       = v0;
                *(__nv_bfloat162*)&O[(size_t)(n0 + 8) * CC + o] = v1;
            }
        }
    }
}

// ---------------------------------------------------------------------------
// Sparse attention v4 (hybrid): one warp per (b, n), all 4 heads.
// K pass: coalesced 512B row load (float4/lane, lane owns ch 8l..8l+7),
//   3-shfl segmented head reduce, ONE predicated STS of the logit to smem.
// Softmax: conflict-free smem reads (bank 4i+h), 3+3 group shuffles,
//   weights written in place over logits.
// V pass: broadcast LDS idx + weight, coalesced V row loads, no shuffles.
// ---------------------------------------------------------------------------
__global__ void __launch_bounds__(256)
attn_kernel(const int* __restrict__ mask, const int* __restrict__ aidx)
{
    __shared__ int   sidx[8][64];      // gathered index, -1 if masked
    __shared__ float sl  [8][64][4];   // logits, then softmax weights

    const int wrp = threadIdx.x >> 5, l = threadIdx.x & 31;
    const int gw = blockIdx.x * 8 + wrp;
    const int n  = gw & (NQ - 1);
    const int b  = gw >> 12;

    const float*         qp = g_qt + ((size_t)b * NQ + n) * CC;
    const __nv_bfloat16* Kb = g_kb + (size_t)b * NQ * CC;
    const __nv_bfloat16* Vb = g_vb + (size_t)b * NQ * CC;

    // q channels 8l..8l+7 (head = l>>3)
    float qv[8];
    {
        float4 a = *(const float4*)&qp[8 * l];
        float4 c = *(const float4*)&qp[8 * l + 4];
        qv[0]=a.x; qv[1]=a.y; qv[2]=a.z; qv[3]=a.w;
        qv[4]=c.x; qv[5]=c.y; qv[6]=c.z; qv[7]=c.w;
    }
    // stage indices with mask sentinel
    {
        int i0 = aidx[n * KK + l];
        int i1 = aidx[n * KK + l + 32];
        int m0 = mask[n * KK + l];
        int m1 = mask[n * KK + l + 32];
        sidx[wrp][l]      = m0 ? i0 : -1;
        sidx[wrp][l + 32] = m1 ? i1 : -1;
    }
    __syncwarp();

    const int h = l >> 3, i = l & 7;

    // ---- K pass: coalesced rows, segmented reduce, 1 STS per key ----
    #pragma unroll 4
    for (int key = 0; key < KK; key++) {
        const int idx = sidx[wrp][key];      // broadcast LDS
        if (idx < 0) continue;               // warp-uniform skip
        float kf[8];
        unpack8(((const float4*)(Kb + (size_t)idx * CC))[l], kf);
        float p = 0.f;
        #pragma unroll
        for (int u = 0; u < 8; u++) p += qv[u] * kf[u];
        p += __shfl_xor_sync(~0u, p, 4);
        p += __shfl_xor_sync(~0u, p, 2);
        p += __shfl_xor_sync(~0u, p, 1);
        if (i == (key & 7)) sl[wrp][key][h] = p;   // banks 4*key+h: free
    }
    __syncwarp();

    // ---- softmax per head: lane 8h+i owns keys i+8j (banks 4i+h: free) ----
    float lg[8];
    #pragma unroll
    for (int j = 0; j < 8; j++) {
        int key = i + 8 * j;
        lg[j] = (sidx[wrp][key] >= 0) ? sl[wrp][key][h] : -INFINITY;
    }
    float mx = lg[0];
    #pragma unroll
    for (int j = 1; j < 8; j++) mx = fmaxf(mx, lg[j]);
    mx = fmaxf(mx, __shfl_xor_sync(~0u, mx, 4));
    mx = fmaxf(mx, __shfl_xor_sync(~0u, mx, 2));
    mx = fmaxf(mx, __shfl_xor_sync(~0u, mx, 1));

    float e[8], s = 0.f;
    #pragma unroll
    for (int j = 0; j < 8; j++) { e[j] = __expf(lg[j] - mx); s += e[j]; }
    s += __shfl_xor_sync(~0u, s, 4);
    s += __shfl_xor_sync(~0u, s, 2);
    s += __shfl_xor_sync(~0u, s, 1);
    const float inv = 1.f / s;

    #pragma unroll
    for (int j = 0; j < 8; j++)
        sl[wrp][i + 8 * j][h] = e[j] * inv;
    __syncwarp();

    // ---- V pass: no shuffles ----
    float acc[8] = {0.f,0.f,0.f,0.f,0.f,0.f,0.f,0.f};

    #pragma unroll 4
    for (int key = 0; key < KK; key++) {
        const int idx = sidx[wrp][key];      // broadcast LDS
        if (idx < 0) continue;               // warp-uniform skip
        const float wv = sl[wrp][key][h];    // 4-addr broadcast LDS
        float vf[8];
        unpack8(((const float4*)(Vb + (size_t)idx * CC))[l], vf);
        #pragma unroll
        for (int u = 0; u < 8; u++) acc[u] += wv * vf[u];
    }

    // ---- store, interleaved channel order c_out = d*HEADS + h ----
    float* at = g_at + ((size_t)b * NQ + n) * CC;
    #pragma unroll
    for (int j = 0; j < 8; j++) {
        int c = 8 * l + j;                   // c = 64*h + d
        at[(c & 63) * HEADS + h] = acc[j];
    }
}

// ---------------------------------------------------------------------------
// Output projection + residual (tf32 MMA, cp.async double-buffered):
// Tile 128(o=M) x 128(n=N), 256 threads. grid (NQ/128, CC/128, B).
// ---------------------------------------------------------------------------
#define OUT_SMEM ((2*128*PAD_B * 2) * 4)

__global__ void __launch_bounds__(256)
gemm_out(const float* __restrict__ Wo, const float* __restrict__ bo,
         const float* __restrict__ x,  float* __restrict__ out)
{
    extern __shared__ unsigned smem_dyn[];
    unsigned* As = smem_dyn;                   // [2][128][PAD_B]  Wo [o][c]
    unsigned* Bs = smem_dyn + 2*128*PAD_B;     // [2][128][PAD_B]  at [n][c]

    const int nb = blockIdx.x * 128, ob = blockIdx.y * 128, b = blockIdx.z;
    const float* A = g_at + (size_t)b * NQ * CC;   // [n][c]

    const int tid  = threadIdx.x;
    const int wid  = tid >> 5, lane = tid & 31;
    const int wm   = wid & 1,  wn   = wid >> 1;
    const int g    = lane >> 2, t   = lane & 3;

    const unsigned as_base = (unsigned)__cvta_generic_to_shared(As);
    const unsigned bs_base = (unsigned)__cvta_generic_to_shared(Bs);

    const int r_o = tid >> 3, r_seg = tid & 7;

    #define LOAD_STAGE(s, c0)                                                  \
    {                                                                          \
        _Pragma("unroll")                                                      \
        for (int j = 0; j < 4; j++) {                                          \
            int o = r_o + j * 32;                                              \
            cp16(as_base + (((s)*128 + o) * PAD_B + r_seg * 4) * 4,            \
                 Wo + (size_t)(ob + o) * CC + (c0) + r_seg * 4);               \
        }                                                                      \
        _Pragma("unroll")                                                      \
        for (int j = 0; j < 4; j++) {                                          \
            int n = r_o + j * 32;                                              \
            cp16(bs_base + (((s)*128 + n) * PAD_B + r_seg * 4) * 4,            \
                 A + (size_t)(nb + n) * CC + (c0) + r_seg * 4);                \
        }                                                                      \
        CP_COMMIT();                                                           \
    }

    float acc[4][4][4];
    #pragma unroll
    for (int i = 0; i < 4; i++)
        #pragma unroll
        for (int j = 0; j < 4; j++)
            #pragma unroll
            for (int r = 0; r < 4; r++) acc[i][j][r] = 0.f;

    LOAD_STAGE(0, 0);

    #pragma unroll
    for (int ks = 0; ks < 8; ks++) {
        const int cur = ks & 1;
        if (ks < 7) {
            LOAD_STAGE(1 - cur, (ks + 1) * 32);
            CP_WAIT(1);
        } else {
            CP_WAIT(0);
        }
        __syncthreads();

        #pragma unroll
        for (int k8 = 0; k8 < 32; k8 += 8) {
            unsigned afr[4][4], bfr[4][2];
            #pragma unroll
            for (int mt = 0; mt < 4; mt++) {
                int row = wm * 64 + mt * 16;
                afr[mt][0] = As[(cur*128 + row + g    ) * PAD_B + k8 + t    ];
                afr[mt][1] = As[(cur*128 + row + 8 + g) * PAD_B + k8 + t    ];
                afr[mt][2] = As[(cur*128 + row + g    ) * PAD_B + k8 + 4 + t];
                afr[mt][3] = As[(cur*128 + row + 8 + g) * PAD_B + k8 + 4 + t];
            }
            #pragma unroll
            for (int nt = 0; nt < 4; nt++) {
                int col = wn * 32 + nt * 8;
                bfr[nt][0] = Bs[(cur*128 + col + g) * PAD_B + k8 + t    ];
                bfr[nt][1] = Bs[(cur*128 + col + g) * PAD_B + k8 + 4 + t];
            }
            #pragma unroll
            for (int mt = 0; mt < 4; mt++)
                #pragma unroll
                for (int nt = 0; nt < 4; nt++)
                    mma1688(acc[mt][nt], afr[mt], bfr[nt]);
        }
        __syncthreads();
    }
    #undef LOAD_STAGE

    const float* xp = x   + (size_t)b * CC * NQ;
    float*       op = out + (size_t)b * CC * NQ;
    #pragma unroll
    for (int mt = 0; mt < 4; mt++) {
        int o0 = ob + wm * 64 + mt * 16 + g;
        float bb0 = bo[o0], bb1 = bo[o0 + 8];
        #pragma unroll
        for (int nt = 0; nt < 4; nt++) {
            int n = nb + wn * 32 + nt * 8 + 2 * t;
            size_t base0 = (size_t)o0 * NQ + n;
            size_t base1 = (size_t)(o0 + 8) * NQ + n;
            float2 x0 = *(const float2*)&xp[base0];
            float2 x1 = *(const float2*)&xp[base1];
            float2 v0 = {acc[mt][nt][0] + bb0 + x0.x, acc[mt][nt][1] + bb0 + x0.y};
            float2 v1 = {acc[mt][nt][2] + bb1 + x1.x, acc[mt][nt][3] + bb1 + x1.y};
            *(float2*)&op[base0] = v0;
            *(float2*)&op[base1] = v1;
        }
    }
}

// ---------------------------------------------------------------------------
extern "C" void kernel_launch(void* const* d_in, const int* in_sizes, int n_in,
                              void* d_out, int out_size)
{
    const float* x    = (const float*)d_in[0];
    const int*   mask = (const int*)  d_in[1];
    const int*   aidx = (const int*)  d_in[2];
    const float* gsc  = (const float*)d_in[3];
    const float* gbi  = (const float*)d_in[4];
    const float* wq   = (const float*)d_in[5];
    const float* bq   = (const float*)d_in[6];
    const float* wk   = (const float*)d_in[7];
    const float* bk   = (const float*)d_in[8];
    const float* wv   = (const float*)d_in[9];
    const float* bv   = (const float*)d_in[10];
    const float* wo   = (const float*)d_in[11];
    const float* bo   = (const float*)d_in[12];
    float* out = (float*)d_out;

    cudaFuncSetAttribute(gemm_qkv, cudaFuncAttributeMaxDynamicSharedMemorySize,
                         QKV_SMEM);
    cudaFuncSetAttribute(gemm_out, cudaFuncAttributeMaxDynamicSharedMemorySize,
                         OUT_SMEM);

    gn_stats<<<dim3(GROUPS, BB), 256>>>(x);

    wprep<<<dim3(3, BB), 256>>>(wq, bq, wk, bk, wv, bv, gsc, gbi);

    gemm_qkv<<<dim3(NQ / 128, 6, BB), 256, QKV_SMEM>>>(x);

    attn_kernel<<<BB * NQ / 8, 256>>>(mask, aidx);

    gemm_out<<<dim3(NQ / 128, CC / 128, BB), 256, OUT_SMEM>>>(wo, bo, x, out);
}

// round 9
// speedup vs baseline: 1.5054x; 1.2461x over previous
#include <cuda_runtime.h>
#include <cuda_bf16.h>
#include <math.h>

#define BB     2
#define CC     256
#define NQ     4096
#define HEADS  4
#define DH     64
#define KK     64
#define GROUPS 32
#define CPG    8
#define EPS    1e-6f

#define PAD_A  136      // [c][n] layout pad
#define PAD_B  36       // [row][c] layout pad

// Scratch (device globals; no allocation allowed)
__device__ float         g_qt[BB*NQ*CC];   // Q fp32, [b][n][c]  c = head*64 + d
__device__ __nv_bfloat16 g_kb[BB*NQ*CC];   // K bf16, [b][n][c]
__device__ __nv_bfloat16 g_vb[BB*NQ*CC];   // V bf16, [b][n][c]
__device__ float         g_at[BB*NQ*CC];   // attn out, [b][n][c] c = d*HEADS + h
__device__ float         g_mean[BB][GROUPS];
__device__ float         g_rstd[BB][GROUPS];
__device__ float         g_wp[BB*3*CC*CC]; // GN-folded weights [b][which][o][c]
__device__ float         g_bp[BB*3*CC];    // GN-folded biases

// ---------------------------------------------------------------------------
// helpers
// ---------------------------------------------------------------------------
__device__ __forceinline__ void mma1688(float d[4], const unsigned a[4],
                                        const unsigned b[2]) {
    asm("mma.sync.aligned.m16n8k8.row.col.f32.tf32.tf32.f32 "
        "{%0,%1,%2,%3}, {%4,%5,%6,%7}, {%8,%9}, {%0,%1,%2,%3};"
        : "+f"(d[0]), "+f"(d[1]), "+f"(d[2]), "+f"(d[3])
        : "r"(a[0]), "r"(a[1]), "r"(a[2]), "r"(a[3]),
          "r"(b[0]), "r"(b[1]));
}

__device__ __forceinline__ void cp16(unsigned dst, const void* src) {
    asm volatile("cp.async.cg.shared.global [%0], [%1], 16;"
                 :: "r"(dst), "l"(src));
}
#define CP_COMMIT() asm volatile("cp.async.commit_group;")
#define CP_WAIT(n)  asm volatile("cp.async.wait_group %0;" :: "n"(n))

__device__ __forceinline__ void unpack8(float4 u, float* f) {
    const __nv_bfloat162* p = (const __nv_bfloat162*)&u;
    float2 a = __bfloat1622float2(p[0]);
    float2 b = __bfloat1622float2(p[1]);
    float2 c = __bfloat1622float2(p[2]);
    float2 d = __bfloat1622float2(p[3]);
    f[0]=a.x; f[1]=a.y; f[2]=b.x; f[3]=b.y;
    f[4]=c.x; f[5]=c.y; f[6]=d.x; f[7]=d.y;
}

// ---------------------------------------------------------------------------
// GroupNorm statistics only: grid (GROUPS, B), block 256
// ---------------------------------------------------------------------------
__global__ void gn_stats(const float* __restrict__ x)
{
    const int g = blockIdx.x, b = blockIdx.y;
    const float* xp = x + ((size_t)b*CC + g*CPG) * NQ;
    const int tid = threadIdx.x;
    const int NE  = CPG * NQ;

    float s = 0.f, s2 = 0.f;
    for (int i = tid; i < NE; i += 256) {
        float v = xp[i];
        s += v; s2 += v * v;
    }
    #pragma unroll
    for (int o = 16; o; o >>= 1) {
        s  += __shfl_xor_sync(~0u, s,  o);
        s2 += __shfl_xor_sync(~0u, s2, o);
    }
    __shared__ float shs[8], shs2[8];
    int w = tid >> 5, l = tid & 31;
    if (l == 0) { shs[w] = s; shs2[w] = s2; }
    __syncthreads();
    if (tid == 0) {
        float a = 0.f, c = 0.f;
        #pragma unroll
        for (int i = 0; i < 8; i++) { a += shs[i]; c += shs2[i]; }
        float m   = a / NE;
        float var = c / NE - m * m;
        g_mean[b][g] = m;
        g_rstd[b][g] = rsqrtf(var + EPS);
    }
}

// ---------------------------------------------------------------------------
// Fold GN into QKV weights. grid (3, B, 8), block 256: each z-slice does
// 32 o-rows -> 48 CTAs (was 6; latency-bound straggler fixed).
// ---------------------------------------------------------------------------
__global__ void wprep(const float* __restrict__ wq, const float* __restrict__ bq,
                      const float* __restrict__ wk, const float* __restrict__ bk,
                      const float* __restrict__ wv, const float* __restrict__ bv,
                      const float* __restrict__ gsc, const float* __restrict__ gbi)
{
    const int which = blockIdx.x, b = blockIdx.y;
    const int obase = blockIdx.z * 32;
    const float* W    = which == 0 ? wq : which == 1 ? wk : wv;
    const float* bias = which == 0 ? bq : which == 1 ? bk : bv;

    __shared__ float coef[CC], sub[CC];
    const int tid = threadIdx.x;
    {
        int c = tid;
        int g = c >> 3;
        float r = g_rstd[b][g], m = g_mean[b][g];
        float sc = gsc[c];
        coef[c] = sc * r;
        sub[c]  = gbi[c] - m * r * sc;
    }
    __syncthreads();

    float* Wp = g_wp + (size_t)(b*3 + which) * CC * CC;
    float* bp = g_bp + (b*3 + which) * CC;
    const int wid = tid >> 5, lane = tid & 31;

    #pragma unroll
    for (int oo = 0; oo < 4; oo++) {
        int o = obase + wid + oo * 8;
        float acc = 0.f;
        #pragma unroll
        for (int cb = 0; cb < CC; cb += 32) {
            int c = cb + lane;
            float w = W[(size_t)o * CC + c];
            Wp[(size_t)o * CC + c] = w * coef[c];
            acc += w * sub[c];
        }
        #pragma unroll
        for (int off = 16; off; off >>= 1)
            acc += __shfl_xor_sync(~0u, acc, off);
        if (lane == 0) bp[o] = bias[o] + acc;
    }
}

// ---------------------------------------------------------------------------
// Fused QKV GEMM (tf32 MMA, cp.async double-buffered, GN folded):
// O[b][n][o] = sum_c W'[o][c] * x[b][c][n] + bias'[o]
// Tile 128(n=M) x 128(o=N), 256 threads (8 warps 2x4). grid (NQ/128, 6, B).
// ---------------------------------------------------------------------------
#define QKV_SMEM ((2*32*PAD_A + 2*128*PAD_B) * 4)

__global__ void __launch_bounds__(256)
gemm_qkv(const float* __restrict__ x)
{
    extern __shared__ unsigned smem_dyn[];
    unsigned* As = smem_dyn;                 // [2][32][PAD_A]  x  [c][n]
    unsigned* Bs = smem_dyn + 2*32*PAD_A;    // [2][128][PAD_B] W' [o][c]

    const int nb    = blockIdx.x * 128;
    const int which = blockIdx.y >> 1;
    const int ob    = (blockIdx.y & 1) * 128;
    const int b     = blockIdx.z;

    const float* W    = g_wp + (size_t)(b*3 + which) * CC * CC;
    const float* bias = g_bp + (b*3 + which) * CC;
    const float* X    = x    + (size_t)b * CC * NQ;   // [c][n]

    const int tid  = threadIdx.x;
    const int wid  = tid >> 5, lane = tid & 31;
    const int wm   = wid & 1,  wn   = wid >> 1;
    const int g    = lane >> 2, t   = lane & 3;

    const unsigned as_base = (unsigned)__cvta_generic_to_shared(As);
    const unsigned bs_base = (unsigned)__cvta_generic_to_shared(Bs);

    const int a_c = tid >> 5, a_seg = tid & 31;
    const int b_o = tid >> 3, b_seg = tid & 7;

    #define LOAD_STAGE(s, c0)                                                  \
    {                                                                          \
        _Pragma("unroll")                                                      \
        for (int j = 0; j < 4; j++) {                                          \
            int c = a_c + j * 8;                                               \
            cp16(as_base + (((s)*32 + c) * PAD_A + a_seg * 4) * 4,             \
                 X + (size_t)((c0) + c) * NQ + nb + a_seg * 4);                \
        }                                                                      \
        _Pragma("unroll")                                                      \
        for (int j = 0; j < 4; j++) {                                          \
            int o = b_o + j * 32;                                              \
            cp16(bs_base + (((s)*128 + o) * PAD_B + b_seg * 4) * 4,            \
                 W + (size_t)(ob + o) * CC + (c0) + b_seg * 4);                \
        }                                                                      \
        CP_COMMIT();                                                           \
    }

    float acc[4][4][4];
    #pragma unroll
    for (int i = 0; i < 4; i++)
        #pragma unroll
        for (int j = 0; j < 4; j++)
            #pragma unroll
            for (int r = 0; r < 4; r++) acc[i][j][r] = 0.f;

    LOAD_STAGE(0, 0);

    #pragma unroll
    for (int ks = 0; ks < 8; ks++) {
        const int cur = ks & 1;
        if (ks < 7) {
            LOAD_STAGE(1 - cur, (ks + 1) * 32);
            CP_WAIT(1);
        } else {
            CP_WAIT(0);
        }
        __syncthreads();

        #pragma unroll
        for (int k8 = 0; k8 < 32; k8 += 8) {
            unsigned afr[4][4], bfr[4][2];
            #pragma unroll
            for (int mt = 0; mt < 4; mt++) {
                int row = wm * 64 + mt * 16;
                afr[mt][0] = As[(cur*32 + k8 + t    ) * PAD_A + row + g    ];
                afr[mt][1] = As[(cur*32 + k8 + t    ) * PAD_A + row + 8 + g];
                afr[mt][2] = As[(cur*32 + k8 + 4 + t) * PAD_A + row + g    ];
                afr[mt][3] = As[(cur*32 + k8 + 4 + t) * PAD_A + row + 8 + g];
            }
            #pragma unroll
            for (int nt = 0; nt < 4; nt++) {
                int col = wn * 32 + nt * 8;
                bfr[nt][0] = Bs[(cur*128 + col + g) * PAD_B + k8 + t    ];
                bfr[nt][1] = Bs[(cur*128 + col + g) * PAD_B + k8 + 4 + t];
            }
            #pragma unroll
            for (int mt = 0; mt < 4; mt++)
                #pragma unroll
                for (int nt = 0; nt < 4; nt++)
                    mma1688(acc[mt][nt], afr[mt], bfr[nt]);
        }
        __syncthreads();
    }
    #undef LOAD_STAGE

    if (which == 0) {
        float* O = g_qt + (size_t)b * NQ * CC;
        #pragma unroll
        for (int nt = 0; nt < 4; nt++) {
            int o = ob + wn * 32 + nt * 8 + 2 * t;
            float bb0 = bias[o], bb1 = bias[o + 1];
            #pragma unroll
            for (int mt = 0; mt < 4; mt++) {
                int n0 = nb + wm * 64 + mt * 16 + g;
                float2 v0 = {acc[mt][nt][0] + bb0, acc[mt][nt][1] + bb1};
                float2 v1 = {acc[mt][nt][2] + bb0, acc[mt][nt][3] + bb1};
                *(float2*)&O[(size_t)n0 * CC + o]       = v0;
                *(float2*)&O[(size_t)(n0 + 8) * CC + o] = v1;
            }
        }
    } else {
        __nv_bfloat16* O = (which == 1 ? g_kb : g_vb) + (size_t)b * NQ * CC;
        #pragma unroll
        for (int nt = 0; nt < 4; nt++) {
            int o = ob + wn * 32 + nt * 8 + 2 * t;
            float bb0 = bias[o], bb1 = bias[o + 1];
            #pragma unroll
            for (int mt = 0; mt < 4; mt++) {
                int n0 = nb + wm * 64 + mt * 16 + g;
                __nv_bfloat162 v0 = {__float2bfloat16_rn(acc[mt][nt][0] + bb0),
                                     __float2bfloat16_rn(acc[mt][nt][1] + bb1)};
                __nv_bfloat162 v1 = {__float2bfloat16_rn(acc[mt][nt][2] + bb0),
                                     __float2bfloat16_rn(acc[mt][nt][3] + bb1)};
                *(__nv_bfloat162*)&O[(size_t)n0 * CC + o]       = v0;
                *(__nv_bfloat162*)&O[(size_t)(n0 + 8) * CC + o] = v1;
            }
        }
    }
}

// ---------------------------------------------------------------------------
// Sparse attention v5: one warp per (b, n), all 4 heads, BRANCHLESS.
// Staging compacts active key indices (ballot+popc prefix) to sidx[0..nact).
// K pass: loop over nact, no branches: coalesced row load, 3-shfl segmented
//   head reduce, 1 predicated STS.
// Softmax: slots >= nact read as -inf (predicated select, no branch).
// V pass: loop over nact, no branches.
// ---------------------------------------------------------------------------
__global__ void __launch_bounds__(256)
attn_kernel(const int* __restrict__ mask, const int* __restrict__ aidx)
{
    __shared__ int   sidx[8][64];      // compacted active indices
    __shared__ float sl  [8][64][4];   // logits, then softmax weights

    const int wrp = threadIdx.x >> 5, l = threadIdx.x & 31;
    const int gw = blockIdx.x * 8 + wrp;
    const int n  = gw & (NQ - 1);
    const int b  = gw >> 12;

    const float*         qp = g_qt + ((size_t)b * NQ + n) * CC;
    const __nv_bfloat16* Kb = g_kb + (size_t)b * NQ * CC;
    const __nv_bfloat16* Vb = g_vb + (size_t)b * NQ * CC;

    // q channels 8l..8l+7 (head = l>>3)
    float qv[8];
    {
        float4 a = *(const float4*)&qp[8 * l];
        float4 c = *(const float4*)&qp[8 * l + 4];
        qv[0]=a.x; qv[1]=a.y; qv[2]=a.z; qv[3]=a.w;
        qv[4]=c.x; qv[5]=c.y; qv[6]=c.z; qv[7]=c.w;
    }
    // compact active indices to the front (ballot prefix-sum)
    int nact;
    {
        int i0 = aidx[n * KK + l];
        int i1 = aidx[n * KK + l + 32];
        int m0 = mask[n * KK + l];
        int m1 = mask[n * KK + l + 32];
        unsigned bl0 = __ballot_sync(~0u, m0 != 0);
        unsigned bl1 = __ballot_sync(~0u, m1 != 0);
        int cnt0 = __popc(bl0);
        nact = cnt0 + __popc(bl1);
        unsigned below = (1u << l) - 1u;
        if (m0) sidx[wrp][__popc(bl0 & below)]        = i0;
        if (m1) sidx[wrp][cnt0 + __popc(bl1 & below)] = i1;
    }
    __syncwarp();

    const int h = l >> 3, i = l & 7;

    // ---- K pass: branchless over compacted keys ----
    #pragma unroll 4
    for (int key = 0; key < nact; key++) {
        const int idx = sidx[wrp][key];      // broadcast LDS
        float kf[8];
        unpack8(((const float4*)(Kb + (size_t)idx * CC))[l], kf);
        float p = 0.f;
        #pragma unroll
        for (int u = 0; u < 8; u++) p += qv[u] * kf[u];
        p += __shfl_xor_sync(~0u, p, 4);
        p += __shfl_xor_sync(~0u, p, 2);
        p += __shfl_xor_sync(~0u, p, 1);
        if (i == (key & 7)) sl[wrp][key][h] = p;   // banks 4*key+h: free
    }
    __syncwarp();

    // ---- softmax per head: lane 8h+i owns slots i+8j (banks 4i+h: free) ----
    float lg[8];
    #pragma unroll
    for (int j = 0; j < 8; j++) {
        int key = i + 8 * j;
        lg[j] = (key < nact) ? sl[wrp][key][h] : -INFINITY;
    }
    float mx = lg[0];
    #pragma unroll
    for (int j = 1; j < 8; j++) mx = fmaxf(mx, lg[j]);
    mx = fmaxf(mx, __shfl_xor_sync(~0u, mx, 4));
    mx = fmaxf(mx, __shfl_xor_sync(~0u, mx, 2));
    mx = fmaxf(mx, __shfl_xor_sync(~0u, mx, 1));

    float e[8], s = 0.f;
    #pragma unroll
    for (int j = 0; j < 8; j++) { e[j] = __expf(lg[j] - mx); s += e[j]; }
    s += __shfl_xor_sync(~0u, s, 4);
    s += __shfl_xor_sync(~0u, s, 2);
    s += __shfl_xor_sync(~0u, s, 1);
    const float inv = 1.f / s;

    #pragma unroll
    for (int j = 0; j < 8; j++)
        sl[wrp][i + 8 * j][h] = e[j] * inv;
    __syncwarp();

    // ---- V pass: branchless over compacted keys ----
    float acc[8] = {0.f,0.f,0.f,0.f,0.f,0.f,0.f,0.f};

    #pragma unroll 4
    for (int key = 0; key < nact; key++) {
        const int idx = sidx[wrp][key];      // broadcast LDS
        const float wv = sl[wrp][key][h];    // 4-addr broadcast LDS
        float vf[8];
        unpack8(((const float4*)(Vb + (size_t)idx * CC))[l], vf);
        #pragma unroll
        for (int u = 0; u < 8; u++) acc[u] += wv * vf[u];
    }

    // ---- store, interleaved channel order c_out = d*HEADS + h ----
    float* at = g_at + ((size_t)b * NQ + n) * CC;
    #pragma unroll
    for (int j = 0; j < 8; j++) {
        int c = 8 * l + j;                   // c = 64*h + d
        at[(c & 63) * HEADS + h] = acc[j];
    }
}

// ---------------------------------------------------------------------------
// Output projection + residual (tf32 MMA, cp.async double-buffered):
// Tile 128(o=M) x 128(n=N), 256 threads. grid (NQ/128, CC/128, B).
// ---------------------------------------------------------------------------
#define OUT_SMEM ((2*128*PAD_B * 2) * 4)

__global__ void __launch_bounds__(256)
gemm_out(const float* __restrict__ Wo, const float* __restrict__ bo,
         const float* __restrict__ x,  float* __restrict__ out)
{
    extern __shared__ unsigned smem_dyn[];
    unsigned* As = smem_dyn;                   // [2][128][PAD_B]  Wo [o][c]
    unsigned* Bs = smem_dyn + 2*128*PAD_B;     // [2][128][PAD_B]  at [n][c]

    const int nb = blockIdx.x * 128, ob = blockIdx.y * 128, b = blockIdx.z;
    const float* A = g_at + (size_t)b * NQ * CC;   // [n][c]

    const int tid  = threadIdx.x;
    const int wid  = tid >> 5, lane = tid & 31;
    const int wm   = wid & 1,  wn   = wid >> 1;
    const int g    = lane >> 2, t   = lane & 3;

    const unsigned as_base = (unsigned)__cvta_generic_to_shared(As);
    const unsigned bs_base = (unsigned)__cvta_generic_to_shared(Bs);

    const int r_o = tid >> 3, r_seg = tid & 7;

    #define LOAD_STAGE(s, c0)                                                  \
    {                                                                          \
        _Pragma("unroll")                                                      \
        for (int j = 0; j < 4; j++) {                                          \
            int o = r_o + j * 32;                                              \
            cp16(as_base + (((s)*128 + o) * PAD_B + r_seg * 4) * 4,            \
                 Wo + (size_t)(ob + o) * CC + (c0) + r_seg * 4);               \
        }                                                                      \
        _Pragma("unroll")                                                      \
        for (int j = 0; j < 4; j++) {                                          \
            int n = r_o + j * 32;                                              \
            cp16(bs_base + (((s)*128 + n) * PAD_B + r_seg * 4) * 4,            \
                 A + (size_t)(nb + n) * CC + (c0) + r_seg * 4);                \
        }                                                                      \
        CP_COMMIT();                                                           \
    }

    float acc[4][4][4];
    #pragma unroll
    for (int i = 0; i < 4; i++)
        #pragma unroll
        for (int j = 0; j < 4; j++)
            #pragma unroll
            for (int r = 0; r < 4; r++) acc[i][j][r] = 0.f;

    LOAD_STAGE(0, 0);

    #pragma unroll
    for (int ks = 0; ks < 8; ks++) {
        const int cur = ks & 1;
        if (ks < 7) {
            LOAD_STAGE(1 - cur, (ks + 1) * 32);
            CP_WAIT(1);
        } else {
            CP_WAIT(0);
        }
        __syncthreads();

        #pragma unroll
        for (int k8 = 0; k8 < 32; k8 += 8) {
            unsigned afr[4][4], bfr[4][2];
            #pragma unroll
            for (int mt = 0; mt < 4; mt++) {
                int row = wm * 64 + mt * 16;
                afr[mt][0] = As[(cur*128 + row + g    ) * PAD_B + k8 + t    ];
                afr[mt][1] = As[(cur*128 + row + 8 + g) * PAD_B + k8 + t    ];
                afr[mt][2] = As[(cur*128 + row + g    ) * PAD_B + k8 + 4 + t];
                afr[mt][3] = As[(cur*128 + row + 8 + g) * PAD_B + k8 + 4 + t];
            }
            #pragma unroll
            for (int nt = 0; nt < 4; nt++) {
                int col = wn * 32 + nt * 8;
                bfr[nt][0] = Bs[(cur*128 + col + g) * PAD_B + k8 + t    ];
                bfr[nt][1] = Bs[(cur*128 + col + g) * PAD_B + k8 + 4 + t];
            }
            #pragma unroll
            for (int mt = 0; mt < 4; mt++)
                #pragma unroll
                for (int nt = 0; nt < 4; nt++)
                    mma1688(acc[mt][nt], afr[mt], bfr[nt]);
        }
        __syncthreads();
    }
    #undef LOAD_STAGE

    const float* xp = x   + (size_t)b * CC * NQ;
    float*       op = out + (size_t)b * CC * NQ;
    #pragma unroll
    for (int mt = 0; mt < 4; mt++) {
        int o0 = ob + wm * 64 + mt * 16 + g;
        float bb0 = bo[o0], bb1 = bo[o0 + 8];
        #pragma unroll
        for (int nt = 0; nt < 4; nt++) {
            int n = nb + wn * 32 + nt * 8 + 2 * t;
            size_t base0 = (size_t)o0 * NQ + n;
            size_t base1 = (size_t)(o0 + 8) * NQ + n;
            float2 x0 = *(const float2*)&xp[base0];
            float2 x1 = *(const float2*)&xp[base1];
            float2 v0 = {acc[mt][nt][0] + bb0 + x0.x, acc[mt][nt][1] + bb0 + x0.y};
            float2 v1 = {acc[mt][nt][2] + bb1 + x1.x, acc[mt][nt][3] + bb1 + x1.y};
            *(float2*)&op[base0] = v0;
            *(float2*)&op[base1] = v1;
        }
    }
}

// ---------------------------------------------------------------------------
extern "C" void kernel_launch(void* const* d_in, const int* in_sizes, int n_in,
                              void* d_out, int out_size)
{
    const float* x    = (const float*)d_in[0];
    const int*   mask = (const int*)  d_in[1];
    const int*   aidx = (const int*)  d_in[2];
    const float* gsc  = (const float*)d_in[3];
    const float* gbi  = (const float*)d_in[4];
    const float* wq   = (const float*)d_in[5];
    const float* bq   = (const float*)d_in[6];
    const float* wk   = (const float*)d_in[7];
    const float* bk   = (const float*)d_in[8];
    const float* wv   = (const float*)d_in[9];
    const float* bv   = (const float*)d_in[10];
    const float* wo   = (const float*)d_in[11];
    const float* bo   = (const float*)d_in[12];
    float* out = (float*)d_out;

    cudaFuncSetAttribute(gemm_qkv, cudaFuncAttributeMaxDynamicSharedMemorySize,
                         QKV_SMEM);
    cudaFuncSetAttribute(gemm_out, cudaFuncAttributeMaxDynamicSharedMemorySize,
                         OUT_SMEM);

    gn_stats<<<dim3(GROUPS, BB), 256>>>(x);

    wprep<<<dim3(3, BB, 8), 256>>>(wq, bq, wk, bk, wv, bv, gsc, gbi);

    gemm_qkv<<<dim3(NQ / 128, 6, BB), 256, QKV_SMEM>>>(x);

    attn_kernel<<<BB * NQ / 8, 256>>>(mask, aidx);

    gemm_out<<<dim3(NQ / 128, CC / 128, BB), 256, OUT_SMEM>>>(wo, bo, x, out);
}

// round 10
// speedup vs baseline: 1.6816x; 1.1171x over previous
#include <cuda_runtime.h>
#include <cuda_bf16.h>
#include <math.h>

#define BB     2
#define CC     256
#define NQ     4096
#define HEADS  4
#define DH     64
#define KK     64
#define GROUPS 32
#define CPG    8
#define EPS    1e-6f

#define PADK   40       // bf16 elems per k=32 smem row (80B, 20 words): conflict-free

// Scratch (device globals; no allocation allowed)
__device__ __nv_bfloat16 g_xt [BB*NQ*CC];   // x^T bf16, [b][n][c]
__device__ __nv_bfloat16 g_qb [BB*NQ*CC];   // Q bf16, [b][n][c]  c = head*64 + d
__device__ __nv_bfloat16 g_kb [BB*NQ*CC];   // K bf16, [b][n][c]
__device__ __nv_bfloat16 g_vb [BB*NQ*CC];   // V bf16, [b][n][c]
__device__ __nv_bfloat16 g_atb[BB*NQ*CC];   // attn out bf16, [b][n][c] c = d*HEADS+h
__device__ float         g_mean[BB][GROUPS];
__device__ float         g_rstd[BB][GROUPS];
__device__ __nv_bfloat16 g_wpb[BB*3*CC*CC]; // GN-folded qkv weights bf16 [b][w][o][c]
__device__ __nv_bfloat16 g_wob[CC*CC];      // Wo bf16 [o][c]
__device__ float         g_bp [BB*3*CC];    // GN-folded biases fp32

// ---------------------------------------------------------------------------
// helpers
// ---------------------------------------------------------------------------
__device__ __forceinline__ void mma_bf16(float d[4], const unsigned a[4],
                                         const unsigned b[2]) {
    asm("mma.sync.aligned.m16n8k16.row.col.f32.bf16.bf16.f32 "
        "{%0,%1,%2,%3}, {%4,%5,%6,%7}, {%8,%9}, {%0,%1,%2,%3};"
        : "+f"(d[0]), "+f"(d[1]), "+f"(d[2]), "+f"(d[3])
        : "r"(a[0]), "r"(a[1]), "r"(a[2]), "r"(a[3]),
          "r"(b[0]), "r"(b[1]));
}

__device__ __forceinline__ void cp16(unsigned dst, const void* src) {
    asm volatile("cp.async.cg.shared.global [%0], [%1], 16;"
                 :: "r"(dst), "l"(src));
}
#define CP_COMMIT() asm volatile("cp.async.commit_group;")
#define CP_WAIT(n)  asm volatile("cp.async.wait_group %0;" :: "n"(n))

__device__ __forceinline__ void unpack8(float4 u, float* f) {
    const __nv_bfloat162* p = (const __nv_bfloat162*)&u;
    float2 a = __bfloat1622float2(p[0]);
    float2 b = __bfloat1622float2(p[1]);
    float2 c = __bfloat1622float2(p[2]);
    float2 d = __bfloat1622float2(p[3]);
    f[0]=a.x; f[1]=a.y; f[2]=b.x; f[3]=b.y;
    f[4]=c.x; f[5]=c.y; f[6]=d.x; f[7]=d.y;
}

// ---------------------------------------------------------------------------
// x transpose + bf16: x [b][c][n] fp32 -> g_xt [b][n][c] bf16
// grid (NQ/32, CC/32, B), block (32, 8)
// ---------------------------------------------------------------------------
__global__ void xpose(const float* __restrict__ x)
{
    __shared__ float t[32][33];
    const int b = blockIdx.z;
    const int n0 = blockIdx.x * 32, c0 = blockIdx.y * 32;
    const float* xp = x + (size_t)b * CC * NQ;
    const int tx = threadIdx.x, ty = threadIdx.y;

    #pragma unroll
    for (int k = 0; k < 4; k++) {
        int cl = k * 8 + ty;
        t[cl][tx] = xp[(size_t)(c0 + cl) * NQ + n0 + tx];
    }
    __syncthreads();
    __nv_bfloat16* o = g_xt + (size_t)b * NQ * CC;
    #pragma unroll
    for (int k = 0; k < 4; k++) {
        int nl = k * 8 + ty;
        o[(size_t)(n0 + nl) * CC + c0 + tx] = __float2bfloat16_rn(t[tx][nl]);
    }
}

// ---------------------------------------------------------------------------
// GroupNorm statistics only: grid (GROUPS, B), block 256
// ---------------------------------------------------------------------------
__global__ void gn_stats(const float* __restrict__ x)
{
    const int g = blockIdx.x, b = blockIdx.y;
    const float* xp = x + ((size_t)b*CC + g*CPG) * NQ;
    const int tid = threadIdx.x;
    const int NE  = CPG * NQ;

    float s = 0.f, s2 = 0.f;
    for (int i = tid; i < NE; i += 256) {
        float v = xp[i];
        s += v; s2 += v * v;
    }
    #pragma unroll
    for (int o = 16; o; o >>= 1) {
        s  += __shfl_xor_sync(~0u, s,  o);
        s2 += __shfl_xor_sync(~0u, s2, o);
    }
    __shared__ float shs[8], shs2[8];
    int w = tid >> 5, l = tid & 31;
    if (l == 0) { shs[w] = s; shs2[w] = s2; }
    __syncthreads();
    if (tid == 0) {
        float a = 0.f, c = 0.f;
        #pragma unroll
        for (int i = 0; i < 8; i++) { a += shs[i]; c += shs2[i]; }
        float m   = a / NE;
        float var = c / NE - m * m;
        g_mean[b][g] = m;
        g_rstd[b][g] = rsqrtf(var + EPS);
    }
}

// ---------------------------------------------------------------------------
// Weight prep: grid (4, B, 8), block 256.
// which 0..2: GN-folded qkv weights -> bf16, folded bias -> fp32.
// which 3:    Wo -> bf16 (plain convert; b-redundant identical writes).
// ---------------------------------------------------------------------------
__global__ void wprep(const float* __restrict__ wq, const float* __restrict__ bq,
                      const float* __restrict__ wk, const float* __restrict__ bk,
                      const float* __restrict__ wv, const float* __restrict__ bv,
                      const float* __restrict__ wo,
                      const float* __restrict__ gsc, const float* __restrict__ gbi)
{
    const int which = blockIdx.x, b = blockIdx.y;
    const int obase = blockIdx.z * 32;
    const int tid = threadIdx.x;
    const int wid = tid >> 5, lane = tid & 31;

    if (which == 3) {
        #pragma unroll
        for (int oo = 0; oo < 4; oo++) {
            int o = obase + wid + oo * 8;
            #pragma unroll
            for (int cb = 0; cb < CC; cb += 32) {
                int c = cb + lane;
                g_wob[(size_t)o * CC + c] =
                    __float2bfloat16_rn(wo[(size_t)o * CC + c]);
            }
        }
        return;
    }

    const float* W    = which == 0 ? wq : which == 1 ? wk : wv;
    const float* bias = which == 0 ? bq : which == 1 ? bk : bv;

    __shared__ float coef[CC], sub[CC];
    {
        int c = tid;
        int g = c >> 3;
        float r = g_rstd[b][g], m = g_mean[b][g];
        float sc = gsc[c];
        coef[c] = sc * r;
        sub[c]  = gbi[c] - m * r * sc;
    }
    __syncthreads();

    __nv_bfloat16* Wp = g_wpb + (size_t)(b*3 + which) * CC * CC;
    float* bp = g_bp + (b*3 + which) * CC;

    #pragma unroll
    for (int oo = 0; oo < 4; oo++) {
        int o = obase + wid + oo * 8;
        float acc = 0.f;
        #pragma unroll
        for (int cb = 0; cb < CC; cb += 32) {
            int c = cb + lane;
            float w = W[(size_t)o * CC + c];
            Wp[(size_t)o * CC + c] = __float2bfloat16_rn(w * coef[c]);
            acc += w * sub[c];
        }
        #pragma unroll
        for (int off = 16; off; off >>= 1)
            acc += __shfl_xor_sync(~0u, acc, off);
        if (lane == 0) bp[o] = bias[o] + acc;
    }
}

// ---------------------------------------------------------------------------
// Fused QKV GEMM (bf16 m16n8k16 MMA, cp.async double-buffered, GN folded):
// O[b][n][o] = sum_c x^T[n][c] * W'[o][c] + bias'[o]   (M = n, N = o)
// Tile 128x128, k-step 32, 256 threads (8 warps 2x4). grid (NQ/128, 6, B).
// Epilogue writes bf16x2 pairs directly into [n][c] layout.
// ---------------------------------------------------------------------------
#define GEMM_SMEM (2 * 2 * 128 * PADK * 2)   // 2 ops x 2 stages x 128 x PADK bf16

__global__ void __launch_bounds__(256)
gemm_qkv()
{
    extern __shared__ __nv_bfloat16 smem_bf[];
    __nv_bfloat16* As = smem_bf;                    // [2][128][PADK] x^T [n][k]
    __nv_bfloat16* Bs = smem_bf + 2*128*PADK;       // [2][128][PADK] W'  [o][k]
    const unsigned* As32 = (const unsigned*)As;
    const unsigned* Bs32 = (const unsigned*)Bs;

    const int nb    = blockIdx.x * 128;
    const int which = blockIdx.y >> 1;
    const int ob    = (blockIdx.y & 1) * 128;
    const int b     = blockIdx.z;

    const __nv_bfloat16* Xt = g_xt  + (size_t)b * NQ * CC;
    const __nv_bfloat16* W  = g_wpb + (size_t)(b*3 + which) * CC * CC;
    const float* bias = g_bp + (b*3 + which) * CC;

    const int tid  = threadIdx.x;
    const int wid  = tid >> 5, lane = tid & 31;
    const int wm   = wid & 1,  wn   = wid >> 1;
    const int g    = lane >> 2, t   = lane & 3;

    const unsigned as_base = (unsigned)__cvta_generic_to_shared(As);
    const unsigned bs_base = (unsigned)__cvta_generic_to_shared(Bs);

    const int cp_r = tid >> 2, cp_s = tid & 3;   // 64 rows x 4 chunks per pass

    #define LOAD_STAGE(s, c0)                                                  \
    {                                                                          \
        _Pragma("unroll")                                                      \
        for (int j = 0; j < 2; j++) {                                          \
            int row = cp_r + j * 64;                                           \
            cp16(as_base + (((s)*128 + row) * PADK + cp_s * 8) * 2,            \
                 Xt + (size_t)(nb + row) * CC + (c0) + cp_s * 8);              \
            cp16(bs_base + (((s)*128 + row) * PADK + cp_s * 8) * 2,            \
                 W  + (size_t)(ob + row) * CC + (c0) + cp_s * 8);              \
        }                                                                      \
        CP_COMMIT();                                                           \
    }

    float acc[4][4][4];
    #pragma unroll
    for (int i = 0; i < 4; i++)
        #pragma unroll
        for (int j = 0; j < 4; j++)
            #pragma unroll
            for (int r = 0; r < 4; r++) acc[i][j][r] = 0.f;

    LOAD_STAGE(0, 0);

    #pragma unroll
    for (int ks = 0; ks < 8; ks++) {
        const int cur = ks & 1;
        if (ks < 7) {
            LOAD_STAGE(1 - cur, (ks + 1) * 32);
            CP_WAIT(1);
        } else {
            CP_WAIT(0);
        }
        __syncthreads();

        #pragma unroll
        for (int kk = 0; kk < 2; kk++) {
            unsigned afr[4][4], bfr[4][2];
            #pragma unroll
            for (int mt = 0; mt < 4; mt++) {
                int base = (cur*128 + wm*64 + mt*16 + g) * (PADK/2) + kk*8 + t;
                afr[mt][0] = As32[base];
                afr[mt][1] = As32[base + 8*(PADK/2)];
                afr[mt][2] = As32[base + 4];
                afr[mt][3] = As32[base + 8*(PADK/2) + 4];
            }
            #pragma unroll
            for (int nt = 0; nt < 4; nt++) {
                int base = (cur*128 + wn*32 + nt*8 + g) * (PADK/2) + kk*8 + t;
                bfr[nt][0] = Bs32[base];
                bfr[nt][1] = Bs32[base + 4];
            }
            #pragma unroll
            for (int mt = 0; mt < 4; mt++)
                #pragma unroll
                for (int nt = 0; nt < 4; nt++)
                    mma_bf16(acc[mt][nt], afr[mt], bfr[nt]);
        }
        __syncthreads();
    }
    #undef LOAD_STAGE

    __nv_bfloat16* O = (which == 0 ? g_qb : which == 1 ? g_kb : g_vb)
                       + (size_t)b * NQ * CC;
    #pragma unroll
    for (int nt = 0; nt < 4; nt++) {
        int o = ob + wn*32 + nt*8 + 2*t;
        float bb0 = bias[o], bb1 = bias[o + 1];
        #pragma unroll
        for (int mt = 0; mt < 4; mt++) {
            int n0 = nb + wm*64 + mt*16 + g;
            __nv_bfloat162 v0 = {__float2bfloat16_rn(acc[mt][nt][0] + bb0),
                                 __float2bfloat16_rn(acc[mt][nt][1] + bb1)};
            __nv_bfloat162 v1 = {__float2bfloat16_rn(acc[mt][nt][2] + bb0),
                                 __float2bfloat16_rn(acc[mt][nt][3] + bb1)};
            *(__nv_bfloat162*)&O[(size_t)n0 * CC + o]       = v0;
            *(__nv_bfloat162*)&O[(size_t)(n0 + 8) * CC + o] = v1;
        }
    }
}

// ---------------------------------------------------------------------------
// Sparse attention (round-9 branchless compaction; Q bf16, output bf16)
// ---------------------------------------------------------------------------
__global__ void __launch_bounds__(256)
attn_kernel(const int* __restrict__ mask, const int* __restrict__ aidx)
{
    __shared__ int   sidx[8][64];
    __shared__ float sl  [8][64][4];

    const int wrp = threadIdx.x >> 5, l = threadIdx.x & 31;
    const int gw = blockIdx.x * 8 + wrp;
    const int n  = gw & (NQ - 1);
    const int b  = gw >> 12;

    const __nv_bfloat16* qp = g_qb + ((size_t)b * NQ + n) * CC;
    const __nv_bfloat16* Kb = g_kb + (size_t)b * NQ * CC;
    const __nv_bfloat16* Vb = g_vb + (size_t)b * NQ * CC;

    float qv[8];
    unpack8(*(const float4*)(qp + 8 * l), qv);

    int nact;
    {
        int i0 = aidx[n * KK + l];
        int i1 = aidx[n * KK + l + 32];
        int m0 = mask[n * KK + l];
        int m1 = mask[n * KK + l + 32];
        unsigned bl0 = __ballot_sync(~0u, m0 != 0);
        unsigned bl1 = __ballot_sync(~0u, m1 != 0);
        int cnt0 = __popc(bl0);
        nact = cnt0 + __popc(bl1);
        unsigned below = (1u << l) - 1u;
        if (m0) sidx[wrp][__popc(bl0 & below)]        = i0;
        if (m1) sidx[wrp][cnt0 + __popc(bl1 & below)] = i1;
    }
    __syncwarp();

    const int h = l >> 3, i = l & 7;

    #pragma unroll 4
    for (int key = 0; key < nact; key++) {
        const int idx = sidx[wrp][key];
        float kf[8];
        unpack8(((const float4*)(Kb + (size_t)idx * CC))[l], kf);
        float p = 0.f;
        #pragma unroll
        for (int u = 0; u < 8; u++) p += qv[u] * kf[u];
        p += __shfl_xor_sync(~0u, p, 4);
        p += __shfl_xor_sync(~0u, p, 2);
        p += __shfl_xor_sync(~0u, p, 1);
        if (i == (key & 7)) sl[wrp][key][h] = p;
    }
    __syncwarp();

    float lg[8];
    #pragma unroll
    for (int j = 0; j < 8; j++) {
        int key = i + 8 * j;
        lg[j] = (key < nact) ? sl[wrp][key][h] : -INFINITY;
    }
    float mx = lg[0];
    #pragma unroll
    for (int j = 1; j < 8; j++) mx = fmaxf(mx, lg[j]);
    mx = fmaxf(mx, __shfl_xor_sync(~0u, mx, 4));
    mx = fmaxf(mx, __shfl_xor_sync(~0u, mx, 2));
    mx = fmaxf(mx, __shfl_xor_sync(~0u, mx, 1));

    float e[8], s = 0.f;
    #pragma unroll
    for (int j = 0; j < 8; j++) { e[j] = __expf(lg[j] - mx); s += e[j]; }
    s += __shfl_xor_sync(~0u, s, 4);
    s += __shfl_xor_sync(~0u, s, 2);
    s += __shfl_xor_sync(~0u, s, 1);
    const float inv = 1.f / s;

    #pragma unroll
    for (int j = 0; j < 8; j++)
        sl[wrp][i + 8 * j][h] = e[j] * inv;
    __syncwarp();

    float acc[8] = {0.f,0.f,0.f,0.f,0.f,0.f,0.f,0.f};

    #pragma unroll 4
    for (int key = 0; key < nact; key++) {
        const int idx = sidx[wrp][key];
        const float wv = sl[wrp][key][h];
        float vf[8];
        unpack8(((const float4*)(Vb + (size_t)idx * CC))[l], vf);
        #pragma unroll
        for (int u = 0; u < 8; u++) acc[u] += wv * vf[u];
    }

    __nv_bfloat16* at = g_atb + ((size_t)b * NQ + n) * CC;
    #pragma unroll
    for (int j = 0; j < 8; j++) {
        int c = 8 * l + j;                   // c = 64*h + d
        at[(c & 63) * HEADS + h] = __float2bfloat16_rn(acc[j]);
    }
}

// ---------------------------------------------------------------------------
// Output projection + residual (bf16 MMA):
// out[b][o][n] = x[b][o][n] + sum_c Wo[o][c] * at[n][c] + bo[o]  (M=o, N=n)
// Tile 128x128, 256 threads. grid (NQ/128, CC/128, B).
// ---------------------------------------------------------------------------
__global__ void __launch_bounds__(256)
gemm_out(const float* __restrict__ bo,
         const float* __restrict__ x,  float* __restrict__ out)
{
    extern __shared__ __nv_bfloat16 smem_bf[];
    __nv_bfloat16* As = smem_bf;                    // [2][128][PADK] Wo [o][k]
    __nv_bfloat16* Bs = smem_bf + 2*128*PADK;       // [2][128][PADK] at [n][k]
    const unsigned* As32 = (const unsigned*)As;
    const unsigned* Bs32 = (const unsigned*)Bs;

    const int nb = blockIdx.x * 128, ob = blockIdx.y * 128, b = blockIdx.z;
    const __nv_bfloat16* A = g_atb + (size_t)b * NQ * CC;

    const int tid  = threadIdx.x;
    const int wid  = tid >> 5, lane = tid & 31;
    const int wm   = wid & 1,  wn   = wid >> 1;
    const int g    = lane >> 2, t   = lane & 3;

    const unsigned as_base = (unsigned)__cvta_generic_to_shared(As);
    const unsigned bs_base = (unsigned)__cvta_generic_to_shared(Bs);

    const int cp_r = tid >> 2, cp_s = tid & 3;

    #define LOAD_STAGE(s, c0)                                                  \
    {                                                                          \
        _Pragma("unroll")                                                      \
        for (int j = 0; j < 2; j++) {                                          \
            int row = cp_r + j * 64;                                           \
            cp16(as_base + (((s)*128 + row) * PADK + cp_s * 8) * 2,            \
                 g_wob + (size_t)(ob + row) * CC + (c0) + cp_s * 8);           \
            cp16(bs_base + (((s)*128 + row) * PADK + cp_s * 8) * 2,            \
                 A + (size_t)(nb + row) * CC + (c0) + cp_s * 8);               \
        }                                                                      \
        CP_COMMIT();                                                           \
    }

    float acc[4][4][4];
    #pragma unroll
    for (int i = 0; i < 4; i++)
        #pragma unroll
        for (int j = 0; j < 4; j++)
            #pragma unroll
            for (int r = 0; r < 4; r++) acc[i][j][r] = 0.f;

    LOAD_STAGE(0, 0);

    #pragma unroll
    for (int ks = 0; ks < 8; ks++) {
        const int cur = ks & 1;
        if (ks < 7) {
            LOAD_STAGE(1 - cur, (ks + 1) * 32);
            CP_WAIT(1);
        } else {
            CP_WAIT(0);
        }
        __syncthreads();

        #pragma unroll
        for (int kk = 0; kk < 2; kk++) {
            unsigned afr[4][4], bfr[4][2];
            #pragma unroll
            for (int mt = 0; mt < 4; mt++) {
                int base = (cur*128 + wm*64 + mt*16 + g) * (PADK/2) + kk*8 + t;
                afr[mt][0] = As32[base];
                afr[mt][1] = As32[base + 8*(PADK/2)];
                afr[mt][2] = As32[base + 4];
                afr[mt][3] = As32[base + 8*(PADK/2) + 4];
            }
            #pragma unroll
            for (int nt = 0; nt < 4; nt++) {
                int base = (cur*128 + wn*32 + nt*8 + g) * (PADK/2) + kk*8 + t;
                bfr[nt][0] = Bs32[base];
                bfr[nt][1] = Bs32[base + 4];
            }
            #pragma unroll
            for (int mt = 0; mt < 4; mt++)
                #pragma unroll
                for (int nt = 0; nt < 4; nt++)
                    mma_bf16(acc[mt][nt], afr[mt], bfr[nt]);
        }
        __syncthreads();
    }
    #undef LOAD_STAGE

    const float* xp = x   + (size_t)b * CC * NQ;
    float*       op = out + (size_t)b * CC * NQ;
    #pragma unroll
    for (int mt = 0; mt < 4; mt++) {
        int o0 = ob + wm*64 + mt*16 + g;
        float bb0 = bo[o0], bb1 = bo[o0 + 8];
        #pragma unroll
        for (int nt = 0; nt < 4; nt++) {
            int n = nb + wn*32 + nt*8 + 2*t;
            size_t base0 = (size_t)o0 * NQ + n;
            size_t base1 = (size_t)(o0 + 8) * NQ + n;
            float2 x0 = *(const float2*)&xp[base0];
            float2 x1 = *(const float2*)&xp[base1];
            float2 v0 = {acc[mt][nt][0] + bb0 + x0.x, acc[mt][nt][1] + bb0 + x0.y};
            float2 v1 = {acc[mt][nt][2] + bb1 + x1.x, acc[mt][nt][3] + bb1 + x1.y};
            *(float2*)&op[base0] = v0;
            *(float2*)&op[base1] = v1;
        }
    }
}

// ---------------------------------------------------------------------------
extern "C" void kernel_launch(void* const* d_in, const int* in_sizes, int n_in,
                              void* d_out, int out_size)
{
    const float* x    = (const float*)d_in[0];
    const int*   mask = (const int*)  d_in[1];
    const int*   aidx = (const int*)  d_in[2];
    const float* gsc  = (const float*)d_in[3];
    const float* gbi  = (const float*)d_in[4];
    const float* wq   = (const float*)d_in[5];
    const float* bq   = (const float*)d_in[6];
    const float* wk   = (const float*)d_in[7];
    const float* bk   = (const float*)d_in[8];
    const float* wv   = (const float*)d_in[9];
    const float* bv   = (const float*)d_in[10];
    const float* wo   = (const float*)d_in[11];
    const float* bo   = (const float*)d_in[12];
    float* out = (float*)d_out;

    cudaFuncSetAttribute(gemm_qkv, cudaFuncAttributeMaxDynamicSharedMemorySize,
                         GEMM_SMEM);
    cudaFuncSetAttribute(gemm_out, cudaFuncAttributeMaxDynamicSharedMemorySize,
                         GEMM_SMEM);

    xpose<<<dim3(NQ / 32, CC / 32, BB), dim3(32, 8)>>>(x);

    gn_stats<<<dim3(GROUPS, BB), 256>>>(x);

    wprep<<<dim3(4, BB, 8), 256>>>(wq, bq, wk, bk, wv, bv, wo, gsc, gbi);

    gemm_qkv<<<dim3(NQ / 128, 6, BB), 256, GEMM_SMEM>>>();

    attn_kernel<<<BB * NQ / 8, 256>>>(mask, aidx);

    gemm_out<<<dim3(NQ / 128, CC / 128, BB), 256, GEMM_SMEM>>>(bo, x, out);
}

// round 11
// speedup vs baseline: 1.8345x; 1.0910x over previous
#include <cuda_runtime.h>
#include <cuda_bf16.h>
#include <math.h>

#define BB     2
#define CC     256
#define NQ     4096
#define HEADS  4
#define DH     64
#define KK     64
#define GROUPS 32
#define CPG    8
#define EPS    1e-6f

#define PADK   40       // bf16 elems per k=32 smem row (80B): conflict-free frags

// Scratch (device globals; no allocation allowed)
__device__ __nv_bfloat16 g_xt [BB*NQ*CC];   // x^T bf16, [b][n][c]
__device__ __nv_bfloat16 g_qb [BB*NQ*CC];   // Q bf16, [b][n][c]  c = head*64 + d
__device__ __nv_bfloat16 g_kb [BB*NQ*CC];   // K bf16, [b][n][c]
__device__ __nv_bfloat16 g_vb [BB*NQ*CC];   // V bf16, [b][n][c]
__device__ __nv_bfloat16 g_atb[BB*NQ*CC];   // attn out bf16, [b][n][c] c=d*HEADS+h
__device__ float         g_mean[BB][GROUPS];
__device__ float         g_rstd[BB][GROUPS];
__device__ __nv_bfloat16 g_wpb[BB*3*CC*CC]; // GN-folded qkv weights bf16
__device__ __nv_bfloat16 g_wob[CC*CC];      // Wo bf16 [o][c]
__device__ float         g_bp [BB*3*CC];    // GN-folded biases fp32

// ---------------------------------------------------------------------------
// helpers
// ---------------------------------------------------------------------------
__device__ __forceinline__ void mma_bf16(float d[4], const unsigned a[4],
                                         const unsigned b[2]) {
    asm("mma.sync.aligned.m16n8k16.row.col.f32.bf16.bf16.f32 "
        "{%0,%1,%2,%3}, {%4,%5,%6,%7}, {%8,%9}, {%0,%1,%2,%3};"
        : "+f"(d[0]), "+f"(d[1]), "+f"(d[2]), "+f"(d[3])
        : "r"(a[0]), "r"(a[1]), "r"(a[2]), "r"(a[3]),
          "r"(b[0]), "r"(b[1]));
}

__device__ __forceinline__ void cp16(unsigned dst, const void* src) {
    asm volatile("cp.async.cg.shared.global [%0], [%1], 16;"
                 :: "r"(dst), "l"(src));
}
#define CP_COMMIT() asm volatile("cp.async.commit_group;")
#define CP_WAIT(n)  asm volatile("cp.async.wait_group %0;" :: "n"(n))

// packed f32x2 helpers (sm_103a dual-f32 pipe)
__device__ __forceinline__ unsigned long long pk2(unsigned lo, unsigned hi) {
    unsigned long long r;
    asm("mov.b64 %0, {%1,%2};" : "=l"(r) : "r"(lo), "r"(hi));
    return r;
}
__device__ __forceinline__ void upk2(unsigned long long v, float& lo, float& hi) {
    unsigned a, b;
    asm("mov.b64 {%0,%1}, %2;" : "=r"(a), "=r"(b) : "l"(v));
    lo = __uint_as_float(a); hi = __uint_as_float(b);
}
__device__ __forceinline__ unsigned long long bfx2(unsigned u) {
    return pk2(u << 16, u & 0xFFFF0000u);   // bf16x2 -> packed f32x2
}
__device__ __forceinline__ void ffma2(unsigned long long& d,
                                      unsigned long long a,
                                      unsigned long long b) {
    asm("fma.rn.f32x2 %0, %1, %2, %0;" : "+l"(d) : "l"(a), "l"(b));
}

// ---------------------------------------------------------------------------
// x transpose + bf16: x [b][c][n] fp32 -> g_xt [b][n][c] bf16
// ---------------------------------------------------------------------------
__global__ void xpose(const float* __restrict__ x)
{
    __shared__ float t[32][33];
    const int b = blockIdx.z;
    const int n0 = blockIdx.x * 32, c0 = blockIdx.y * 32;
    const float* xp = x + (size_t)b * CC * NQ;
    const int tx = threadIdx.x, ty = threadIdx.y;

    #pragma unroll
    for (int k = 0; k < 4; k++) {
        int cl = k * 8 + ty;
        t[cl][tx] = xp[(size_t)(c0 + cl) * NQ + n0 + tx];
    }
    __syncthreads();
    __nv_bfloat16* o = g_xt + (size_t)b * NQ * CC;
    #pragma unroll
    for (int k = 0; k < 4; k++) {
        int nl = k * 8 + ty;
        o[(size_t)(n0 + nl) * CC + c0 + tx] = __float2bfloat16_rn(t[tx][nl]);
    }
}

// ---------------------------------------------------------------------------
// GroupNorm statistics only
// ---------------------------------------------------------------------------
__global__ void gn_stats(const float* __restrict__ x)
{
    const int g = blockIdx.x, b = blockIdx.y;
    const float* xp = x + ((size_t)b*CC + g*CPG) * NQ;
    const int tid = threadIdx.x;
    const int NE  = CPG * NQ;

    float s = 0.f, s2 = 0.f;
    for (int i = tid; i < NE; i += 256) {
        float v = xp[i];
        s += v; s2 += v * v;
    }
    #pragma unroll
    for (int o = 16; o; o >>= 1) {
        s  += __shfl_xor_sync(~0u, s,  o);
        s2 += __shfl_xor_sync(~0u, s2, o);
    }
    __shared__ float shs[8], shs2[8];
    int w = tid >> 5, l = tid & 31;
    if (l == 0) { shs[w] = s; shs2[w] = s2; }
    __syncthreads();
    if (tid == 0) {
        float a = 0.f, c = 0.f;
        #pragma unroll
        for (int i = 0; i < 8; i++) { a += shs[i]; c += shs2[i]; }
        float m   = a / NE;
        float var = c / NE - m * m;
        g_mean[b][g] = m;
        g_rstd[b][g] = rsqrtf(var + EPS);
    }
}

// ---------------------------------------------------------------------------
// Weight prep: grid (4, B, 8), block 256
// ---------------------------------------------------------------------------
__global__ void wprep(const float* __restrict__ wq, const float* __restrict__ bq,
                      const float* __restrict__ wk, const float* __restrict__ bk,
                      const float* __restrict__ wv, const float* __restrict__ bv,
                      const float* __restrict__ wo,
                      const float* __restrict__ gsc, const float* __restrict__ gbi)
{
    const int which = blockIdx.x, b = blockIdx.y;
    const int obase = blockIdx.z * 32;
    const int tid = threadIdx.x;
    const int wid = tid >> 5, lane = tid & 31;

    if (which == 3) {
        #pragma unroll
        for (int oo = 0; oo < 4; oo++) {
            int o = obase + wid + oo * 8;
            #pragma unroll
            for (int cb = 0; cb < CC; cb += 32) {
                int c = cb + lane;
                g_wob[(size_t)o * CC + c] =
                    __float2bfloat16_rn(wo[(size_t)o * CC + c]);
            }
        }
        return;
    }

    const float* W    = which == 0 ? wq : which == 1 ? wk : wv;
    const float* bias = which == 0 ? bq : which == 1 ? bk : bv;

    __shared__ float coef[CC], sub[CC];
    {
        int c = tid;
        int g = c >> 3;
        float r = g_rstd[b][g], m = g_mean[b][g];
        float sc = gsc[c];
        coef[c] = sc * r;
        sub[c]  = gbi[c] - m * r * sc;
    }
    __syncthreads();

    __nv_bfloat16* Wp = g_wpb + (size_t)(b*3 + which) * CC * CC;
    float* bp = g_bp + (b*3 + which) * CC;

    #pragma unroll
    for (int oo = 0; oo < 4; oo++) {
        int o = obase + wid + oo * 8;
        float acc = 0.f;
        #pragma unroll
        for (int cb = 0; cb < CC; cb += 32) {
            int c = cb + lane;
            float w = W[(size_t)o * CC + c];
            Wp[(size_t)o * CC + c] = __float2bfloat16_rn(w * coef[c]);
            acc += w * sub[c];
        }
        #pragma unroll
        for (int off = 16; off; off >>= 1)
            acc += __shfl_xor_sync(~0u, acc, off);
        if (lane == 0) bp[o] = bias[o] + acc;
    }
}

// ---------------------------------------------------------------------------
// Fused QKV GEMM (bf16 MMA, 3-stage cp.async, 2 CTAs/SM):
// O[b][n][o] = sum_c x^T[n][c] * W'[o][c] + bias'[o]
// Tile 128x128, k-step 32. grid (NQ/128, 6, B).
// ---------------------------------------------------------------------------
#define GEMM_SMEM (3 * 2 * 128 * PADK * 2)   // 3 stages x 2 ops x 128 x PADK bf16

__global__ void __launch_bounds__(256, 2)
gemm_qkv()
{
    extern __shared__ __nv_bfloat16 smem_bf[];
    __nv_bfloat16* As = smem_bf;                    // [3][128][PADK]
    __nv_bfloat16* Bs = smem_bf + 3*128*PADK;       // [3][128][PADK]
    const unsigned* As32 = (const unsigned*)As;
    const unsigned* Bs32 = (const unsigned*)Bs;

    const int nb    = blockIdx.x * 128;
    const int which = blockIdx.y >> 1;
    const int ob    = (blockIdx.y & 1) * 128;
    const int b     = blockIdx.z;

    const __nv_bfloat16* Xt = g_xt  + (size_t)b * NQ * CC;
    const __nv_bfloat16* W  = g_wpb + (size_t)(b*3 + which) * CC * CC;
    const float* bias = g_bp + (b*3 + which) * CC;

    const int tid  = threadIdx.x;
    const int wid  = tid >> 5, lane = tid & 31;
    const int wm   = wid & 1,  wn   = wid >> 1;
    const int g    = lane >> 2, t   = lane & 3;

    const unsigned as_base = (unsigned)__cvta_generic_to_shared(As);
    const unsigned bs_base = (unsigned)__cvta_generic_to_shared(Bs);

    const int cp_r = tid >> 2, cp_s = tid & 3;

    #define LOAD_STAGE(s, c0)                                                  \
    {                                                                          \
        _Pragma("unroll")                                                      \
        for (int j = 0; j < 2; j++) {                                          \
            int row = cp_r + j * 64;                                           \
            cp16(as_base + (((s)*128 + row) * PADK + cp_s * 8) * 2,            \
                 Xt + (size_t)(nb + row) * CC + (c0) + cp_s * 8);              \
            cp16(bs_base + (((s)*128 + row) * PADK + cp_s * 8) * 2,            \
                 W  + (size_t)(ob + row) * CC + (c0) + cp_s * 8);              \
        }                                                                      \
        CP_COMMIT();                                                           \
    }

    float acc[4][4][4];
    #pragma unroll
    for (int i = 0; i < 4; i++)
        #pragma unroll
        for (int j = 0; j < 4; j++)
            #pragma unroll
            for (int r = 0; r < 4; r++) acc[i][j][r] = 0.f;

    LOAD_STAGE(0, 0);
    LOAD_STAGE(1, 32);

    #pragma unroll
    for (int ks = 0; ks < 8; ks++) {
        const int cur = ks % 3;
        if (ks < 6) { LOAD_STAGE((ks + 2) % 3, (ks + 2) * 32); CP_WAIT(2); }
        else if (ks == 6) { CP_WAIT(1); }
        else { CP_WAIT(0); }
        __syncthreads();

        #pragma unroll
        for (int kk = 0; kk < 2; kk++) {
            unsigned afr[4][4], bfr[4][2];
            #pragma unroll
            for (int mt = 0; mt < 4; mt++) {
                int base = (cur*128 + wm*64 + mt*16 + g) * (PADK/2) + kk*8 + t;
                afr[mt][0] = As32[base];
                afr[mt][1] = As32[base + 8*(PADK/2)];
                afr[mt][2] = As32[base + 4];
                afr[mt][3] = As32[base + 8*(PADK/2) + 4];
            }
            #pragma unroll
            for (int nt = 0; nt < 4; nt++) {
                int base = (cur*128 + wn*32 + nt*8 + g) * (PADK/2) + kk*8 + t;
                bfr[nt][0] = Bs32[base];
                bfr[nt][1] = Bs32[base + 4];
            }
            #pragma unroll
            for (int mt = 0; mt < 4; mt++)
                #pragma unroll
                for (int nt = 0; nt < 4; nt++)
                    mma_bf16(acc[mt][nt], afr[mt], bfr[nt]);
        }
        __syncthreads();
    }
    #undef LOAD_STAGE

    __nv_bfloat16* O = (which == 0 ? g_qb : which == 1 ? g_kb : g_vb)
                       + (size_t)b * NQ * CC;
    #pragma unroll
    for (int nt = 0; nt < 4; nt++) {
        int o = ob + wn*32 + nt*8 + 2*t;
        float bb0 = bias[o], bb1 = bias[o + 1];
        #pragma unroll
        for (int mt = 0; mt < 4; mt++) {
            int n0 = nb + wm*64 + mt*16 + g;
            __nv_bfloat162 v0 = {__float2bfloat16_rn(acc[mt][nt][0] + bb0),
                                 __float2bfloat16_rn(acc[mt][nt][1] + bb1)};
            __nv_bfloat162 v1 = {__float2bfloat16_rn(acc[mt][nt][2] + bb0),
                                 __float2bfloat16_rn(acc[mt][nt][3] + bb1)};
            *(__nv_bfloat162*)&O[(size_t)n0 * CC + o]       = v0;
            *(__nv_bfloat162*)&O[(size_t)(n0 + 8) * CC + o] = v1;
        }
    }
}

// ---------------------------------------------------------------------------
// Sparse attention: 128-thread blocks (occupancy), packed f32x2 FMA.
// ---------------------------------------------------------------------------
__global__ void __launch_bounds__(128)
attn_kernel(const int* __restrict__ mask, const int* __restrict__ aidx)
{
    __shared__ int   sidx[4][64];
    __shared__ float sl  [4][64][4];

    const int wrp = threadIdx.x >> 5, l = threadIdx.x & 31;
    const int gw = blockIdx.x * 4 + wrp;
    const int n  = gw & (NQ - 1);
    const int b  = gw >> 12;

    const __nv_bfloat16* qp = g_qb + ((size_t)b * NQ + n) * CC;
    const __nv_bfloat16* Kb = g_kb + (size_t)b * NQ * CC;
    const __nv_bfloat16* Vb = g_vb + (size_t)b * NQ * CC;

    // q channels 8l..8l+7 pre-packed as f32x2
    unsigned long long q2[4];
    {
        uint4 qw = *(const uint4*)(qp + 8 * l);
        q2[0] = bfx2(qw.x); q2[1] = bfx2(qw.y);
        q2[2] = bfx2(qw.z); q2[3] = bfx2(qw.w);
    }

    int nact;
    {
        int i0 = aidx[n * KK + l];
        int i1 = aidx[n * KK + l + 32];
        int m0 = mask[n * KK + l];
        int m1 = mask[n * KK + l + 32];
        unsigned bl0 = __ballot_sync(~0u, m0 != 0);
        unsigned bl1 = __ballot_sync(~0u, m1 != 0);
        int cnt0 = __popc(bl0);
        nact = cnt0 + __popc(bl1);
        unsigned below = (1u << l) - 1u;
        if (m0) sidx[wrp][__popc(bl0 & below)]        = i0;
        if (m1) sidx[wrp][cnt0 + __popc(bl1 & below)] = i1;
    }
    __syncwarp();

    const int h = l >> 3, i = l & 7;

    // ---- K pass (f32x2 dot, 3-shfl segmented head reduce, 1 STS) ----
    #pragma unroll 4
    for (int key = 0; key < nact; key++) {
        const int idx = sidx[wrp][key];
        uint4 kw = ((const uint4*)(Kb + (size_t)idx * CC))[l];
        unsigned long long a2 = 0ull;
        ffma2(a2, q2[0], bfx2(kw.x));
        ffma2(a2, q2[1], bfx2(kw.y));
        ffma2(a2, q2[2], bfx2(kw.z));
        ffma2(a2, q2[3], bfx2(kw.w));
        float plo, phi; upk2(a2, plo, phi);
        float p = plo + phi;
        p += __shfl_xor_sync(~0u, p, 4);
        p += __shfl_xor_sync(~0u, p, 2);
        p += __shfl_xor_sync(~0u, p, 1);
        if (i == (key & 7)) sl[wrp][key][h] = p;
    }
    __syncwarp();

    // ---- softmax per head ----
    float lg[8];
    #pragma unroll
    for (int j = 0; j < 8; j++) {
        int key = i + 8 * j;
        lg[j] = (key < nact) ? sl[wrp][key][h] : -INFINITY;
    }
    float mx = lg[0];
    #pragma unroll
    for (int j = 1; j < 8; j++) mx = fmaxf(mx, lg[j]);
    mx = fmaxf(mx, __shfl_xor_sync(~0u, mx, 4));
    mx = fmaxf(mx, __shfl_xor_sync(~0u, mx, 2));
    mx = fmaxf(mx, __shfl_xor_sync(~0u, mx, 1));

    float e[8], s = 0.f;
    #pragma unroll
    for (int j = 0; j < 8; j++) { e[j] = __expf(lg[j] - mx); s += e[j]; }
    s += __shfl_xor_sync(~0u, s, 4);
    s += __shfl_xor_sync(~0u, s, 2);
    s += __shfl_xor_sync(~0u, s, 1);
    const float inv = 1.f / s;

    #pragma unroll
    for (int j = 0; j < 8; j++)
        sl[wrp][i + 8 * j][h] = e[j] * inv;
    __syncwarp();

    // ---- V pass (f32x2 accumulate) ----
    unsigned long long vacc[4] = {0ull, 0ull, 0ull, 0ull};

    #pragma unroll 4
    for (int key = 0; key < nact; key++) {
        const int idx = sidx[wrp][key];
        const float wv = sl[wrp][key][h];
        unsigned wu = __float_as_uint(wv);
        unsigned long long w2 = pk2(wu, wu);
        uint4 vw = ((const uint4*)(Vb + (size_t)idx * CC))[l];
        ffma2(vacc[0], w2, bfx2(vw.x));
        ffma2(vacc[1], w2, bfx2(vw.y));
        ffma2(vacc[2], w2, bfx2(vw.z));
        ffma2(vacc[3], w2, bfx2(vw.w));
    }

    float acc[8];
    upk2(vacc[0], acc[0], acc[1]);
    upk2(vacc[1], acc[2], acc[3]);
    upk2(vacc[2], acc[4], acc[5]);
    upk2(vacc[3], acc[6], acc[7]);

    __nv_bfloat16* at = g_atb + ((size_t)b * NQ + n) * CC;
    #pragma unroll
    for (int j = 0; j < 8; j++) {
        int c = 8 * l + j;                   // c = 64*h + d
        at[(c & 63) * HEADS + h] = __float2bfloat16_rn(acc[j]);
    }
}

// ---------------------------------------------------------------------------
// Output projection + residual (bf16 MMA, 3-stage cp.async, 2 CTAs/SM)
// ---------------------------------------------------------------------------
__global__ void __launch_bounds__(256, 2)
gemm_out(const float* __restrict__ bo,
         const float* __restrict__ x,  float* __restrict__ out)
{
    extern __shared__ __nv_bfloat16 smem_bf[];
    __nv_bfloat16* As = smem_bf;                    // [3][128][PADK] Wo
    __nv_bfloat16* Bs = smem_bf + 3*128*PADK;       // [3][128][PADK] at
    const unsigned* As32 = (const unsigned*)As;
    const unsigned* Bs32 = (const unsigned*)Bs;

    const int nb = blockIdx.x * 128, ob = blockIdx.y * 128, b = blockIdx.z;
    const __nv_bfloat16* A = g_atb + (size_t)b * NQ * CC;

    const int tid  = threadIdx.x;
    const int wid  = tid >> 5, lane = tid & 31;
    const int wm   = wid & 1,  wn   = wid >> 1;
    const int g    = lane >> 2, t   = lane & 3;

    const unsigned as_base = (unsigned)__cvta_generic_to_shared(As);
    const unsigned bs_base = (unsigned)__cvta_generic_to_shared(Bs);

    const int cp_r = tid >> 2, cp_s = tid & 3;

    #define LOAD_STAGE(s, c0)                                                  \
    {                                                                          \
        _Pragma("unroll")                                                      \
        for (int j = 0; j < 2; j++) {                                          \
            int row = cp_r + j * 64;                                           \
            cp16(as_base + (((s)*128 + row) * PADK + cp_s * 8) * 2,            \
                 g_wob + (size_t)(ob + row) * CC + (c0) + cp_s * 8);           \
            cp16(bs_base + (((s)*128 + row) * PADK + cp_s * 8) * 2,            \
                 A + (size_t)(nb + row) * CC + (c0) + cp_s * 8);               \
        }                                                                      \
        CP_COMMIT();                                                           \
    }

    float acc[4][4][4];
    #pragma unroll
    for (int i = 0; i < 4; i++)
        #pragma unroll
        for (int j = 0; j < 4; j++)
            #pragma unroll
            for (int r = 0; r < 4; r++) acc[i][j][r] = 0.f;

    LOAD_STAGE(0, 0);
    LOAD_STAGE(1, 32);

    #pragma unroll
    for (int ks = 0; ks < 8; ks++) {
        const int cur = ks % 3;
        if (ks < 6) { LOAD_STAGE((ks + 2) % 3, (ks + 2) * 32); CP_WAIT(2); }
        else if (ks == 6) { CP_WAIT(1); }
        else { CP_WAIT(0); }
        __syncthreads();

        #pragma unroll
        for (int kk = 0; kk < 2; kk++) {
            unsigned afr[4][4], bfr[4][2];
            #pragma unroll
            for (int mt = 0; mt < 4; mt++) {
                int base = (cur*128 + wm*64 + mt*16 + g) * (PADK/2) + kk*8 + t;
                afr[mt][0] = As32[base];
                afr[mt][1] = As32[base + 8*(PADK/2)];
                afr[mt][2] = As32[base + 4];
                afr[mt][3] = As32[base + 8*(PADK/2) + 4];
            }
            #pragma unroll
            for (int nt = 0; nt < 4; nt++) {
                int base = (cur*128 + wn*32 + nt*8 + g) * (PADK/2) + kk*8 + t;
                bfr[nt][0] = Bs32[base];
                bfr[nt][1] = Bs32[base + 4];
            }
            #pragma unroll
            for (int mt = 0; mt < 4; mt++)
                #pragma unroll
                for (int nt = 0; nt < 4; nt++)
                    mma_bf16(acc[mt][nt], afr[mt], bfr[nt]);
        }
        __syncthreads();
    }
    #undef LOAD_STAGE

    const float* xp = x   + (size_t)b * CC * NQ;
    float*       op = out + (size_t)b * CC * NQ;
    #pragma unroll
    for (int mt = 0; mt < 4; mt++) {
        int o0 = ob + wm*64 + mt*16 + g;
        float bb0 = bo[o0], bb1 = bo[o0 + 8];
        #pragma unroll
        for (int nt = 0; nt < 4; nt++) {
            int n = nb + wn*32 + nt*8 + 2*t;
            size_t base0 = (size_t)o0 * NQ + n;
            size_t base1 = (size_t)(o0 + 8) * NQ + n;
            float2 x0 = *(const float2*)&xp[base0];
            float2 x1 = *(const float2*)&xp[base1];
            float2 v0 = {acc[mt][nt][0] + bb0 + x0.x, acc[mt][nt][1] + bb0 + x0.y};
            float2 v1 = {acc[mt][nt][2] + bb1 + x1.x, acc[mt][nt][3] + bb1 + x1.y};
            *(float2*)&op[base0] = v0;
            *(float2*)&op[base1] = v1;
        }
    }
}

// ---------------------------------------------------------------------------
extern "C" void kernel_launch(void* const* d_in, const int* in_sizes, int n_in,
                              void* d_out, int out_size)
{
    const float* x    = (const float*)d_in[0];
    const int*   mask = (const int*)  d_in[1];
    const int*   aidx = (const int*)  d_in[2];
    const float* gsc  = (const float*)d_in[3];
    const float* gbi  = (const float*)d_in[4];
    const float* wq   = (const float*)d_in[5];
    const float* bq   = (const float*)d_in[6];
    const float* wk   = (const float*)d_in[7];
    const float* bk   = (const float*)d_in[8];
    const float* wv   = (const float*)d_in[9];
    const float* bv   = (const float*)d_in[10];
    const float* wo   = (const float*)d_in[11];
    const float* bo   = (const float*)d_in[12];
    float* out = (float*)d_out;

    cudaFuncSetAttribute(gemm_qkv, cudaFuncAttributeMaxDynamicSharedMemorySize,
                         GEMM_SMEM);
    cudaFuncSetAttribute(gemm_out, cudaFuncAttributeMaxDynamicSharedMemorySize,
                         GEMM_SMEM);

    xpose<<<dim3(NQ / 32, CC / 32, BB), dim3(32, 8)>>>(x);

    gn_stats<<<dim3(GROUPS, BB), 256>>>(x);

    wprep<<<dim3(4, BB, 8), 256>>>(wq, bq, wk, bk, wv, bv, wo, gsc, gbi);

    gemm_qkv<<<dim3(NQ / 128, 6, BB), 256, GEMM_SMEM>>>();

    attn_kernel<<<BB * NQ / 4, 128>>>(mask, aidx);

    gemm_out<<<dim3(NQ / 128, CC / 128, BB), 256, GEMM_SMEM>>>(bo, x, out);
}

// round 12
// speedup vs baseline: 1.8969x; 1.0340x over previous
#include <cuda_runtime.h>
#include <cuda_bf16.h>
#include <math.h>

#define BB     2
#define CC     256
#define NQ     4096
#define HEADS  4
#define DH     64
#define KK     64
#define GROUPS 32
#define CPG    8
#define EPS    1e-6f

#define PADK   40       // bf16 elems per k=32 smem row (80B): conflict-free frags
#define NTILES (NQ/32)  // 128 n-tiles for gn partials

// Scratch (device globals; no allocation allowed)
__device__ __nv_bfloat16 g_xt [BB*NQ*CC];   // x^T bf16, [b][n][c]
__device__ __nv_bfloat16 g_qb [BB*NQ*CC];   // Q bf16, [b][n][c]  c = head*64 + d
__device__ __nv_bfloat16 g_kb [BB*NQ*CC];   // K bf16, [b][n][c]
__device__ __nv_bfloat16 g_vb [BB*NQ*CC];   // V bf16, [b][n][c]
__device__ __nv_bfloat16 g_atb[BB*NQ*CC];   // attn out bf16, [b][n][c] c=d*HEADS+h
__device__ float         g_ps [BB*GROUPS*NTILES];   // gn partial sums
__device__ float         g_ps2[BB*GROUPS*NTILES];   // gn partial sumsq
__device__ float         g_mean[BB][GROUPS];
__device__ float         g_rstd[BB][GROUPS];
__device__ __nv_bfloat16 g_wpb[BB*3*CC*CC]; // GN-folded qkv weights bf16
__device__ __nv_bfloat16 g_wob[CC*CC];      // Wo bf16 [o][c]
__device__ float         g_bp [BB*3*CC];    // GN-folded biases fp32

// ---------------------------------------------------------------------------
// helpers
// ---------------------------------------------------------------------------
__device__ __forceinline__ void mma_bf16(float d[4], const unsigned a[4],
                                         const unsigned b[2]) {
    asm("mma.sync.aligned.m16n8k16.row.col.f32.bf16.bf16.f32 "
        "{%0,%1,%2,%3}, {%4,%5,%6,%7}, {%8,%9}, {%0,%1,%2,%3};"
        : "+f"(d[0]), "+f"(d[1]), "+f"(d[2]), "+f"(d[3])
        : "r"(a[0]), "r"(a[1]), "r"(a[2]), "r"(a[3]),
          "r"(b[0]), "r"(b[1]));
}

__device__ __forceinline__ void cp16(unsigned dst, const void* src) {
    asm volatile("cp.async.cg.shared.global [%0], [%1], 16;"
                 :: "r"(dst), "l"(src));
}
#define CP_COMMIT() asm volatile("cp.async.commit_group;")
#define CP_WAIT(n)  asm volatile("cp.async.wait_group %0;" :: "n"(n))

// packed f32x2 helpers (sm_103a dual-f32 pipe)
__device__ __forceinline__ unsigned long long pk2(unsigned lo, unsigned hi) {
    unsigned long long r;
    asm("mov.b64 %0, {%1,%2};" : "=l"(r) : "r"(lo), "r"(hi));
    return r;
}
__device__ __forceinline__ void upk2(unsigned long long v, float& lo, float& hi) {
    unsigned a, b;
    asm("mov.b64 {%0,%1}, %2;" : "=r"(a), "=r"(b) : "l"(v));
    lo = __uint_as_float(a); hi = __uint_as_float(b);
}
__device__ __forceinline__ unsigned long long bfx2(unsigned u) {
    return pk2(u << 16, u & 0xFFFF0000u);   // bf16x2 -> packed f32x2
}
__device__ __forceinline__ void ffma2(unsigned long long& d,
                                      unsigned long long a,
                                      unsigned long long b) {
    asm("fma.rn.f32x2 %0, %1, %2, %0;" : "+l"(d) : "l"(a), "l"(b));
}

// ---------------------------------------------------------------------------
// Fused transpose + GN partial stats:
// x [b][c][n] fp32 -> g_xt [b][n][c] bf16, plus per-(b,group,ntile) s/s2.
// grid (NQ/32, CC/32, B), block (32, 8). The 4 values each thread loads
// belong to 4 different groups (k = group-within-tile).
// ---------------------------------------------------------------------------
__global__ void xpose_gn(const float* __restrict__ x)
{
    __shared__ float t[32][33];
    __shared__ float red[8][4][2];   // [ty][k][{s,s2}]
    const int b = blockIdx.z;
    const int n0 = blockIdx.x * 32, c0 = blockIdx.y * 32;
    const float* xp = x + (size_t)b * CC * NQ;
    const int tx = threadIdx.x, ty = threadIdx.y;

    float vs[4];
    #pragma unroll
    for (int k = 0; k < 4; k++) {
        int cl = k * 8 + ty;
        float v = xp[(size_t)(c0 + cl) * NQ + n0 + tx];
        t[cl][tx] = v;
        vs[k] = v;
    }
    // per-k (= per-group) warp reduction over tx
    #pragma unroll
    for (int k = 0; k < 4; k++) {
        float s = vs[k], s2 = vs[k] * vs[k];
        #pragma unroll
        for (int o = 16; o; o >>= 1) {
            s  += __shfl_xor_sync(~0u, s,  o);
            s2 += __shfl_xor_sync(~0u, s2, o);
        }
        if (tx == 0) { red[ty][k][0] = s; red[ty][k][1] = s2; }
    }
    __syncthreads();

    // transposed bf16 write
    __nv_bfloat16* o = g_xt + (size_t)b * NQ * CC;
    #pragma unroll
    for (int k = 0; k < 4; k++) {
        int nl = k * 8 + ty;
        o[(size_t)(n0 + nl) * CC + c0 + tx] = __float2bfloat16_rn(t[tx][nl]);
    }

    // tile-level group partials (4 groups per tile)
    if (ty == 0 && tx < 4) {
        float s = 0.f, s2 = 0.f;
        #pragma unroll
        for (int y = 0; y < 8; y++) { s += red[y][tx][0]; s2 += red[y][tx][1]; }
        int grp = blockIdx.y * 4 + tx;
        g_ps [(b * GROUPS + grp) * NTILES + blockIdx.x] = s;
        g_ps2[(b * GROUPS + grp) * NTILES + blockIdx.x] = s2;
    }
}

// ---------------------------------------------------------------------------
// GN finish: reduce 128 partials per (b, group). grid (GROUPS, B), block 128.
// ---------------------------------------------------------------------------
__global__ void gn_finish()
{
    const int g = blockIdx.x, b = blockIdx.y;
    const int tid = threadIdx.x;
    float s  = g_ps [(b * GROUPS + g) * NTILES + tid];
    float s2 = g_ps2[(b * GROUPS + g) * NTILES + tid];
    #pragma unroll
    for (int o = 16; o; o >>= 1) {
        s  += __shfl_xor_sync(~0u, s,  o);
        s2 += __shfl_xor_sync(~0u, s2, o);
    }
    __shared__ float as[4], as2[4];
    int w = tid >> 5;
    if ((tid & 31) == 0) { as[w] = s; as2[w] = s2; }
    __syncthreads();
    if (tid == 0) {
        float ts = 0.f, ts2 = 0.f;
        #pragma unroll
        for (int i = 0; i < 4; i++) { ts += as[i]; ts2 += as2[i]; }
        const float NE = (float)(CPG * NQ);
        float m = ts / NE;
        float var = ts2 / NE - m * m;
        g_mean[b][g] = m;
        g_rstd[b][g] = rsqrtf(var + EPS);
    }
}

// ---------------------------------------------------------------------------
// Weight prep: grid (4, B, 8), block 256
// ---------------------------------------------------------------------------
__global__ void wprep(const float* __restrict__ wq, const float* __restrict__ bq,
                      const float* __restrict__ wk, const float* __restrict__ bk,
                      const float* __restrict__ wv, const float* __restrict__ bv,
                      const float* __restrict__ wo,
                      const float* __restrict__ gsc, const float* __restrict__ gbi)
{
    const int which = blockIdx.x, b = blockIdx.y;
    const int obase = blockIdx.z * 32;
    const int tid = threadIdx.x;
    const int wid = tid >> 5, lane = tid & 31;

    if (which == 3) {
        #pragma unroll
        for (int oo = 0; oo < 4; oo++) {
            int o = obase + wid + oo * 8;
            #pragma unroll
            for (int cb = 0; cb < CC; cb += 32) {
                int c = cb + lane;
                g_wob[(size_t)o * CC + c] =
                    __float2bfloat16_rn(wo[(size_t)o * CC + c]);
            }
        }
        return;
    }

    const float* W    = which == 0 ? wq : which == 1 ? wk : wv;
    const float* bias = which == 0 ? bq : which == 1 ? bk : bv;

    __shared__ float coef[CC], sub[CC];
    {
        int c = tid;
        int g = c >> 3;
        float r = g_rstd[b][g], m = g_mean[b][g];
        float sc = gsc[c];
        coef[c] = sc * r;
        sub[c]  = gbi[c] - m * r * sc;
    }
    __syncthreads();

    __nv_bfloat16* Wp = g_wpb + (size_t)(b*3 + which) * CC * CC;
    float* bp = g_bp + (b*3 + which) * CC;

    #pragma unroll
    for (int oo = 0; oo < 4; oo++) {
        int o = obase + wid + oo * 8;
        float acc = 0.f;
        #pragma unroll
        for (int cb = 0; cb < CC; cb += 32) {
            int c = cb + lane;
            float w = W[(size_t)o * CC + c];
            Wp[(size_t)o * CC + c] = __float2bfloat16_rn(w * coef[c]);
            acc += w * sub[c];
        }
        #pragma unroll
        for (int off = 16; off; off >>= 1)
            acc += __shfl_xor_sync(~0u, acc, off);
        if (lane == 0) bp[o] = bias[o] + acc;
    }
}

// ---------------------------------------------------------------------------
// Fused QKV GEMM (bf16 MMA, 4-stage cp.async, ONE sync per k-step, 2 CTAs/SM)
// O[b][n][o] = sum_c x^T[n][c] * W'[o][c] + bias'[o]
// Tile 128x128, k-step 32. grid (NQ/128, 6, B).
// ---------------------------------------------------------------------------
#define GEMM_SMEM (4 * 2 * 128 * PADK * 2)   // 4 stages x 2 ops

__global__ void __launch_bounds__(256, 2)
gemm_qkv()
{
    extern __shared__ __nv_bfloat16 smem_bf[];
    __nv_bfloat16* As = smem_bf;                    // [4][128][PADK]
    __nv_bfloat16* Bs = smem_bf + 4*128*PADK;       // [4][128][PADK]
    const unsigned* As32 = (const unsigned*)As;
    const unsigned* Bs32 = (const unsigned*)Bs;

    const int nb    = blockIdx.x * 128;
    const int which = blockIdx.y >> 1;
    const int ob    = (blockIdx.y & 1) * 128;
    const int b     = blockIdx.z;

    const __nv_bfloat16* Xt = g_xt  + (size_t)b * NQ * CC;
    const __nv_bfloat16* W  = g_wpb + (size_t)(b*3 + which) * CC * CC;
    const float* bias = g_bp + (b*3 + which) * CC;

    const int tid  = threadIdx.x;
    const int wid  = tid >> 5, lane = tid & 31;
    const int wm   = wid & 1,  wn   = wid >> 1;
    const int g    = lane >> 2, t   = lane & 3;

    const unsigned as_base = (unsigned)__cvta_generic_to_shared(As);
    const unsigned bs_base = (unsigned)__cvta_generic_to_shared(Bs);

    const int cp_r = tid >> 2, cp_s = tid & 3;

    #define LOAD_STAGE(s, c0)                                                  \
    {                                                                          \
        _Pragma("unroll")                                                      \
        for (int j = 0; j < 2; j++) {                                          \
            int row = cp_r + j * 64;                                           \
            cp16(as_base + (((s)*128 + row) * PADK + cp_s * 8) * 2,            \
                 Xt + (size_t)(nb + row) * CC + (c0) + cp_s * 8);              \
            cp16(bs_base + (((s)*128 + row) * PADK + cp_s * 8) * 2,            \
                 W  + (size_t)(ob + row) * CC + (c0) + cp_s * 8);              \
        }                                                                      \
        CP_COMMIT();                                                           \
    }

    float acc[4][4][4];
    #pragma unroll
    for (int i = 0; i < 4; i++)
        #pragma unroll
        for (int j = 0; j < 4; j++)
            #pragma unroll
            for (int r = 0; r < 4; r++) acc[i][j][r] = 0.f;

    LOAD_STAGE(0, 0);
    LOAD_STAGE(1, 32);
    LOAD_STAGE(2, 64);

    #pragma unroll
    for (int ks = 0; ks < 8; ks++) {
        const int cur = ks & 3;
        if (ks < 6)      { CP_WAIT(2); }
        else if (ks == 6){ CP_WAIT(1); }
        else             { CP_WAIT(0); }
        __syncthreads();
        if (ks < 5) LOAD_STAGE((ks + 3) & 3, (ks + 3) * 32);

        #pragma unroll
        for (int kk = 0; kk < 2; kk++) {
            unsigned afr[4][4], bfr[4][2];
            #pragma unroll
            for (int mt = 0; mt < 4; mt++) {
                int base = (cur*128 + wm*64 + mt*16 + g) * (PADK/2) + kk*8 + t;
                afr[mt][0] = As32[base];
                afr[mt][1] = As32[base + 8*(PADK/2)];
                afr[mt][2] = As32[base + 4];
                afr[mt][3] = As32[base + 8*(PADK/2) + 4];
            }
            #pragma unroll
            for (int nt = 0; nt < 4; nt++) {
                int base = (cur*128 + wn*32 + nt*8 + g) * (PADK/2) + kk*8 + t;
                bfr[nt][0] = Bs32[base];
                bfr[nt][1] = Bs32[base + 4];
            }
            #pragma unroll
            for (int mt = 0; mt < 4; mt++)
                #pragma unroll
                for (int nt = 0; nt < 4; nt++)
                    mma_bf16(acc[mt][nt], afr[mt], bfr[nt]);
        }
    }
    #undef LOAD_STAGE

    __nv_bfloat16* O = (which == 0 ? g_qb : which == 1 ? g_kb : g_vb)
                       + (size_t)b * NQ * CC;
    #pragma unroll
    for (int nt = 0; nt < 4; nt++) {
        int o = ob + wn*32 + nt*8 + 2*t;
        float bb0 = bias[o], bb1 = bias[o + 1];
        #pragma unroll
        for (int mt = 0; mt < 4; mt++) {
            int n0 = nb + wm*64 + mt*16 + g;
            __nv_bfloat162 v0 = {__float2bfloat16_rn(acc[mt][nt][0] + bb0),
                                 __float2bfloat16_rn(acc[mt][nt][1] + bb1)};
            __nv_bfloat162 v1 = {__float2bfloat16_rn(acc[mt][nt][2] + bb0),
                                 __float2bfloat16_rn(acc[mt][nt][3] + bb1)};
            *(__nv_bfloat162*)&O[(size_t)n0 * CC + o]       = v0;
            *(__nv_bfloat162*)&O[(size_t)(n0 + 8) * CC + o] = v1;
        }
    }
}

// ---------------------------------------------------------------------------
// Sparse attention: 128-thread blocks, packed f32x2 FMA (round-11)
// ---------------------------------------------------------------------------
__global__ void __launch_bounds__(128)
attn_kernel(const int* __restrict__ mask, const int* __restrict__ aidx)
{
    __shared__ int   sidx[4][64];
    __shared__ float sl  [4][64][4];

    const int wrp = threadIdx.x >> 5, l = threadIdx.x & 31;
    const int gw = blockIdx.x * 4 + wrp;
    const int n  = gw & (NQ - 1);
    const int b  = gw >> 12;

    const __nv_bfloat16* qp = g_qb + ((size_t)b * NQ + n) * CC;
    const __nv_bfloat16* Kb = g_kb + (size_t)b * NQ * CC;
    const __nv_bfloat16* Vb = g_vb + (size_t)b * NQ * CC;

    unsigned long long q2[4];
    {
        uint4 qw = *(const uint4*)(qp + 8 * l);
        q2[0] = bfx2(qw.x); q2[1] = bfx2(qw.y);
        q2[2] = bfx2(qw.z); q2[3] = bfx2(qw.w);
    }

    int nact;
    {
        int i0 = aidx[n * KK + l];
        int i1 = aidx[n * KK + l + 32];
        int m0 = mask[n * KK + l];
        int m1 = mask[n * KK + l + 32];
        unsigned bl0 = __ballot_sync(~0u, m0 != 0);
        unsigned bl1 = __ballot_sync(~0u, m1 != 0);
        int cnt0 = __popc(bl0);
        nact = cnt0 + __popc(bl1);
        unsigned below = (1u << l) - 1u;
        if (m0) sidx[wrp][__popc(bl0 & below)]        = i0;
        if (m1) sidx[wrp][cnt0 + __popc(bl1 & below)] = i1;
    }
    __syncwarp();

    const int h = l >> 3, i = l & 7;

    #pragma unroll 4
    for (int key = 0; key < nact; key++) {
        const int idx = sidx[wrp][key];
        uint4 kw = ((const uint4*)(Kb + (size_t)idx * CC))[l];
        unsigned long long a2 = 0ull;
        ffma2(a2, q2[0], bfx2(kw.x));
        ffma2(a2, q2[1], bfx2(kw.y));
        ffma2(a2, q2[2], bfx2(kw.z));
        ffma2(a2, q2[3], bfx2(kw.w));
        float plo, phi; upk2(a2, plo, phi);
        float p = plo + phi;
        p += __shfl_xor_sync(~0u, p, 4);
        p += __shfl_xor_sync(~0u, p, 2);
        p += __shfl_xor_sync(~0u, p, 1);
        if (i == (key & 7)) sl[wrp][key][h] = p;
    }
    __syncwarp();

    float lg[8];
    #pragma unroll
    for (int j = 0; j < 8; j++) {
        int key = i + 8 * j;
        lg[j] = (key < nact) ? sl[wrp][key][h] : -INFINITY;
    }
    float mx = lg[0];
    #pragma unroll
    for (int j = 1; j < 8; j++) mx = fmaxf(mx, lg[j]);
    mx = fmaxf(mx, __shfl_xor_sync(~0u, mx, 4));
    mx = fmaxf(mx, __shfl_xor_sync(~0u, mx, 2));
    mx = fmaxf(mx, __shfl_xor_sync(~0u, mx, 1));

    float e[8], s = 0.f;
    #pragma unroll
    for (int j = 0; j < 8; j++) { e[j] = __expf(lg[j] - mx); s += e[j]; }
    s += __shfl_xor_sync(~0u, s, 4);
    s += __shfl_xor_sync(~0u, s, 2);
    s += __shfl_xor_sync(~0u, s, 1);
    const float inv = 1.f / s;

    #pragma unroll
    for (int j = 0; j < 8; j++)
        sl[wrp][i + 8 * j][h] = e[j] * inv;
    __syncwarp();

    unsigned long long vacc[4] = {0ull, 0ull, 0ull, 0ull};

    #pragma unroll 4
    for (int key = 0; key < nact; key++) {
        const int idx = sidx[wrp][key];
        const float wv = sl[wrp][key][h];
        unsigned wu = __float_as_uint(wv);
        unsigned long long w2 = pk2(wu, wu);
        uint4 vw = ((const uint4*)(Vb + (size_t)idx * CC))[l];
        ffma2(vacc[0], w2, bfx2(vw.x));
        ffma2(vacc[1], w2, bfx2(vw.y));
        ffma2(vacc[2], w2, bfx2(vw.z));
        ffma2(vacc[3], w2, bfx2(vw.w));
    }

    float acc[8];
    upk2(vacc[0], acc[0], acc[1]);
    upk2(vacc[1], acc[2], acc[3]);
    upk2(vacc[2], acc[4], acc[5]);
    upk2(vacc[3], acc[6], acc[7]);

    __nv_bfloat16* at = g_atb + ((size_t)b * NQ + n) * CC;
    #pragma unroll
    for (int j = 0; j < 8; j++) {
        int c = 8 * l + j;                   // c = 64*h + d
        at[(c & 63) * HEADS + h] = __float2bfloat16_rn(acc[j]);
    }
}

// ---------------------------------------------------------------------------
// Output projection + residual (bf16 MMA, 4-stage cp.async, one sync/step)
// ---------------------------------------------------------------------------
__global__ void __launch_bounds__(256, 2)
gemm_out(const float* __restrict__ bo,
         const float* __restrict__ x,  float* __restrict__ out)
{
    extern __shared__ __nv_bfloat16 smem_bf[];
    __nv_bfloat16* As = smem_bf;                    // [4][128][PADK] Wo
    __nv_bfloat16* Bs = smem_bf + 4*128*PADK;       // [4][128][PADK] at
    const unsigned* As32 = (const unsigned*)As;
    const unsigned* Bs32 = (const unsigned*)Bs;

    const int nb = blockIdx.x * 128, ob = blockIdx.y * 128, b = blockIdx.z;
    const __nv_bfloat16* A = g_atb + (size_t)b * NQ * CC;

    const int tid  = threadIdx.x;
    const int wid  = tid >> 5, lane = tid & 31;
    const int wm   = wid & 1,  wn   = wid >> 1;
    const int g    = lane >> 2, t   = lane & 3;

    const unsigned as_base = (unsigned)__cvta_generic_to_shared(As);
    const unsigned bs_base = (unsigned)__cvta_generic_to_shared(Bs);

    const int cp_r = tid >> 2, cp_s = tid & 3;

    #define LOAD_STAGE(s, c0)                                                  \
    {                                                                          \
        _Pragma("unroll")                                                      \
        for (int j = 0; j < 2; j++) {                                          \
            int row = cp_r + j * 64;                                           \
            cp16(as_base + (((s)*128 + row) * PADK + cp_s * 8) * 2,            \
                 g_wob + (size_t)(ob + row) * CC + (c0) + cp_s * 8);           \
            cp16(bs_base + (((s)*128 + row) * PADK + cp_s * 8) * 2,            \
                 A + (size_t)(nb + row) * CC + (c0) + cp_s * 8);               \
        }                                                                      \
        CP_COMMIT();                                                           \
    }

    float acc[4][4][4];
    #pragma unroll
    for (int i = 0; i < 4; i++)
        #pragma unroll
        for (int j = 0; j < 4; j++)
            #pragma unroll
            for (int r = 0; r < 4; r++) acc[i][j][r] = 0.f;

    LOAD_STAGE(0, 0);
    LOAD_STAGE(1, 32);
    LOAD_STAGE(2, 64);

    #pragma unroll
    for (int ks = 0; ks < 8; ks++) {
        const int cur = ks & 3;
        if (ks < 6)      { CP_WAIT(2); }
        else if (ks == 6){ CP_WAIT(1); }
        else             { CP_WAIT(0); }
        __syncthreads();
        if (ks < 5) LOAD_STAGE((ks + 3) & 3, (ks + 3) * 32);

        #pragma unroll
        for (int kk = 0; kk < 2; kk++) {
            unsigned afr[4][4], bfr[4][2];
            #pragma unroll
            for (int mt = 0; mt < 4; mt++) {
                int base = (cur*128 + wm*64 + mt*16 + g) * (PADK/2) + kk*8 + t;
                afr[mt][0] = As32[base];
                afr[mt][1] = As32[base + 8*(PADK/2)];
                afr[mt][2] = As32[base + 4];
                afr[mt][3] = As32[base + 8*(PADK/2) + 4];
            }
            #pragma unroll
            for (int nt = 0; nt < 4; nt++) {
                int base = (cur*128 + wn*32 + nt*8 + g) * (PADK/2) + kk*8 + t;
                bfr[nt][0] = Bs32[base];
                bfr[nt][1] = Bs32[base + 4];
            }
            #pragma unroll
            for (int mt = 0; mt < 4; mt++)
                #pragma unroll
                for (int nt = 0; nt < 4; nt++)
                    mma_bf16(acc[mt][nt], afr[mt], bfr[nt]);
        }
    }
    #undef LOAD_STAGE

    const float* xp = x   + (size_t)b * CC * NQ;
    float*       op = out + (size_t)b * CC * NQ;
    #pragma unroll
    for (int mt = 0; mt < 4; mt++) {
        int o0 = ob + wm*64 + mt*16 + g;
        float bb0 = bo[o0], bb1 = bo[o0 + 8];
        #pragma unroll
        for (int nt = 0; nt < 4; nt++) {
            int n = nb + wn*32 + nt*8 + 2*t;
            size_t base0 = (size_t)o0 * NQ + n;
            size_t base1 = (size_t)(o0 + 8) * NQ + n;
            float2 x0 = *(const float2*)&xp[base0];
            float2 x1 = *(const float2*)&xp[base1];
            float2 v0 = {acc[mt][nt][0] + bb0 + x0.x, acc[mt][nt][1] + bb0 + x0.y};
            float2 v1 = {acc[mt][nt][2] + bb1 + x1.x, acc[mt][nt][3] + bb1 + x1.y};
            *(float2*)&op[base0] = v0;
            *(float2*)&op[base1] = v1;
        }
    }
}

// ---------------------------------------------------------------------------
extern "C" void kernel_launch(void* const* d_in, const int* in_sizes, int n_in,
                              void* d_out, int out_size)
{
    const float* x    = (const float*)d_in[0];
    const int*   mask = (const int*)  d_in[1];
    const int*   aidx = (const int*)  d_in[2];
    const float* gsc  = (const float*)d_in[3];
    const float* gbi  = (const float*)d_in[4];
    const float* wq   = (const float*)d_in[5];
    const float* bq   = (const float*)d_in[6];
    const float* wk   = (const float*)d_in[7];
    const float* bk   = (const float*)d_in[8];
    const float* wv   = (const float*)d_in[9];
    const float* bv   = (const float*)d_in[10];
    const float* wo   = (const float*)d_in[11];
    const float* bo   = (const float*)d_in[12];
    float* out = (float*)d_out;

    cudaFuncSetAttribute(gemm_qkv, cudaFuncAttributeMaxDynamicSharedMemorySize,
                         GEMM_SMEM);
    cudaFuncSetAttribute(gemm_out, cudaFuncAttributeMaxDynamicSharedMemorySize,
                         GEMM_SMEM);

    xpose_gn<<<dim3(NQ / 32, CC / 32, BB), dim3(32, 8)>>>(x);

    gn_finish<<<dim3(GROUPS, BB), 128>>>();

    wprep<<<dim3(4, BB, 8), 256>>>(wq, bq, wk, bk, wv, bv, wo, gsc, gbi);

    gemm_qkv<<<dim3(NQ / 128, 6, BB), 256, GEMM_SMEM>>>();

    attn_kernel<<<BB * NQ / 4, 128>>>(mask, aidx);

    gemm_out<<<dim3(NQ / 128, CC / 128, BB), 256, GEMM_SMEM>>>(bo, x, out);
}